// round 1
// baseline (speedup 1.0000x reference)
#include <cuda_runtime.h>

#define EMBEDC 1024
#define HEADSC 16
#define HDIMC  64
#define BC     4
#define SC     1023
#define TC     1024
#define M1     (BC*SC)   // 4092

// Scratch (allocation-free rule: __device__ globals)
__device__ float g_Q[BC*HEADSC*SC*HDIMC];   // [b][h][s][d]
__device__ float g_K[BC*HEADSC*TC*HDIMC];   // [b][h][t][d], t=0 is image token
__device__ float g_V[BC*HEADSC*TC*HDIMC];
__device__ float g_AO[BC*SC*EMBEDC];        // attention output, (B,S,E)

// ---------------------------------------------------------------------------
// Kernel 1: qkv = word @ c_attn_w + bias, scattered into g_Q/g_K/g_V.
// Classic 128x128x16 fp32 SGEMM, 256 threads, 8x8 micro tile.
// ---------------------------------------------------------------------------
__global__ __launch_bounds__(256) void k_qkv(const float* __restrict__ A,
                                             const float* __restrict__ W,
                                             const float* __restrict__ bias)
{
    __shared__ __align__(16) float As[16*132];   // [k][m], pad 132
    __shared__ __align__(16) float Bs[16*132];   // [k][n]
    const int tid = threadIdx.x;
    const int bm = blockIdx.y * 128;
    const int bn = blockIdx.x * 128;
    const int tm = (tid >> 4) * 8;
    const int tn = (tid & 15) * 8;
    float acc[8][8] = {};

    for (int kt = 0; kt < 1024; kt += 16) {
        #pragma unroll
        for (int i = 0; i < 2; i++) {
            int f = tid + i*256;            // 512 float4 of A tile
            int r = f >> 2, c = (f & 3) << 2;
            int gr = bm + r;
            float4 v = make_float4(0.f,0.f,0.f,0.f);
            if (gr < M1) v = *(const float4*)(A + (size_t)gr*1024 + kt + c);
            As[(c+0)*132 + r] = v.x;
            As[(c+1)*132 + r] = v.y;
            As[(c+2)*132 + r] = v.z;
            As[(c+3)*132 + r] = v.w;
        }
        #pragma unroll
        for (int i = 0; i < 2; i++) {
            int f = tid + i*256;
            int r = f >> 5, c = (f & 31) << 2;
            *(float4*)&Bs[r*132 + c] =
                *(const float4*)(W + (size_t)(kt+r)*3072 + bn + c);
        }
        __syncthreads();
        #pragma unroll
        for (int k = 0; k < 16; k++) {
            float av[8], bv[8];
            *(float4*)&av[0] = *(float4*)&As[k*132 + tm];
            *(float4*)&av[4] = *(float4*)&As[k*132 + tm + 4];
            *(float4*)&bv[0] = *(float4*)&Bs[k*132 + tn];
            *(float4*)&bv[4] = *(float4*)&Bs[k*132 + tn + 4];
            #pragma unroll
            for (int i = 0; i < 8; i++)
                #pragma unroll
                for (int j = 0; j < 8; j++)
                    acc[i][j] = fmaf(av[i], bv[j], acc[i][j]);
        }
        __syncthreads();
    }

    // Epilogue: bias + scatter. Column group (8 cols) stays within one head
    // and one qkv region (all boundaries are multiples of 8).
    const int n0 = bn + tn;
    float bb[8];
    #pragma unroll
    for (int j = 0; j < 8; j++) bb[j] = bias[n0 + j];
    const int region = n0 >> 10;       // 0=q,1=k,2=v
    const int w0 = n0 & 1023;
    const int h  = w0 >> 6;
    const int d0 = w0 & 63;

    #pragma unroll
    for (int i = 0; i < 8; i++) {
        int m = bm + tm + i;
        if (m >= M1) continue;
        int b_ = m / SC;
        int s  = m - b_ * SC;
        float* dst;
        size_t idx;
        if (region == 0) {
            dst = g_Q; idx = (((size_t)b_*HEADSC + h)*SC + s)*HDIMC + d0;
        } else if (region == 1) {
            dst = g_K; idx = (((size_t)b_*HEADSC + h)*TC + (s+1))*HDIMC + d0;
        } else {
            dst = g_V; idx = (((size_t)b_*HEADSC + h)*TC + (s+1))*HDIMC + d0;
        }
        float4 v0 = make_float4(acc[i][0]+bb[0], acc[i][1]+bb[1],
                                acc[i][2]+bb[2], acc[i][3]+bb[3]);
        float4 v1 = make_float4(acc[i][4]+bb[4], acc[i][5]+bb[5],
                                acc[i][6]+bb[6], acc[i][7]+bb[7]);
        *(float4*)(dst + idx)     = v0;
        *(float4*)(dst + idx + 4) = v1;
    }
}

// ---------------------------------------------------------------------------
// Kernel 2: image token K/V:  k_img[b][j] = img[b]·uk_w[j,:] + uk_b[j]
// One warp per output element (8192 outputs total).
// ---------------------------------------------------------------------------
__global__ __launch_bounds__(256) void k_img(const float* __restrict__ img,
                                             const float* __restrict__ ukw,
                                             const float* __restrict__ ukb,
                                             const float* __restrict__ uvw,
                                             const float* __restrict__ uvb)
{
    int gw   = (blockIdx.x * blockDim.x + threadIdx.x) >> 5;
    int lane = threadIdx.x & 31;
    int which = gw >> 12;          // 0 -> K, 1 -> V
    int rem = gw & 4095;
    int b_ = rem >> 10;
    int j  = rem & 1023;
    const float* w  = which ? uvw : ukw;
    const float* bb = which ? uvb : ukb;

    const float4* x4 = (const float4*)(img + (size_t)b_*1024);
    const float4* w4 = (const float4*)(w + (size_t)j*1024);
    float s = 0.f;
    for (int e = lane; e < 256; e += 32) {
        float4 a = x4[e], b = w4[e];
        s += a.x*b.x + a.y*b.y + a.z*b.z + a.w*b.w;
    }
    #pragma unroll
    for (int o = 16; o; o >>= 1) s += __shfl_xor_sync(0xffffffffu, s, o);
    if (lane == 0) {
        int h = j >> 6, d = j & 63;
        float* dst = which ? g_V : g_K;
        dst[(((size_t)b_*HEADSC + h)*TC + 0)*HDIMC + d] = s + bb[j];
    }
}

// ---------------------------------------------------------------------------
// Kernel 3: attention. Block = (qt, h, b), 64 queries x full causal key range.
// No running max needed: scores are O(1) and masked -> p=0 exactly (matches
// reference, where exp(-10000 - m) underflows to 0 in fp32).
// ---------------------------------------------------------------------------
__global__ __launch_bounds__(256) void k_attn(const float* __restrict__ amask)
{
    extern __shared__ __align__(16) float sm[];
    float* Qs  = sm;                 // [d][q]  64 x 68
    float* Ks  = Qs + 64*68;         // [d][k]  64 x 68
    float* Vs  = Ks + 64*68;         // [k][d]  64 x 68
    float* Ps  = Vs + 64*68;         // [k][q]  64 x 68
    float* red = Ps + 64*68;         // 64 x 17
    float* msk = red + 64*17;        // 64

    const int tid = threadIdx.x;
    const int qt = blockIdx.x, h = blockIdx.y, b_ = blockIdx.z;
    const int q0 = qt * 64;
    const float* Qg = g_Q + (((size_t)b_*HEADSC + h)*SC) * HDIMC;
    const float* Kg = g_K + (((size_t)b_*HEADSC + h)*TC) * HDIMC;
    const float* Vg = g_V + (((size_t)b_*HEADSC + h)*TC) * HDIMC;

    #pragma unroll
    for (int i = 0; i < 4; i++) {                // load Q tile transposed
        int f = tid + i*256;
        int q = f >> 4, c = (f & 15) << 2;
        int gq = q0 + q;
        float4 v = make_float4(0.f,0.f,0.f,0.f);
        if (gq < SC) v = *(const float4*)(Qg + (size_t)gq*HDIMC + c);
        Qs[(c+0)*68 + q] = v.x;
        Qs[(c+1)*68 + q] = v.y;
        Qs[(c+2)*68 + q] = v.z;
        Qs[(c+3)*68 + q] = v.w;
    }

    const int ty = tid >> 4, tx = tid & 15;
    const int qy = ty * 4, kx = tx * 4, dx = tx * 4;
    float o[4][4] = {};
    float lsum[4] = {0.f,0.f,0.f,0.f};

    const int kmax = min(TC - 1, q0 + 64);   // last valid key index
    const int nkt  = (kmax >> 6) + 1;

    for (int kt = 0; kt < nkt; kt++) {
        const int k0 = kt * 64;
        __syncthreads();                       // protect Ks/Vs/Ps from prev iter
        #pragma unroll
        for (int i = 0; i < 4; i++) {
            int f = tid + i*256;
            int kk = f >> 4, c = (f & 15) << 2;
            float4 v = *(const float4*)(Kg + (size_t)(k0+kk)*HDIMC + c);
            Ks[(c+0)*68 + kk] = v.x;
            Ks[(c+1)*68 + kk] = v.y;
            Ks[(c+2)*68 + kk] = v.z;
            Ks[(c+3)*68 + kk] = v.w;
            *(float4*)&Vs[kk*68 + c] = *(const float4*)(Vg + (size_t)(k0+kk)*HDIMC + c);
        }
        if (tid < 64) {
            int j = k0 + tid;
            msk[tid] = (j == 0) ? 0.f : amask[(size_t)b_*SC + j - 1];
        }
        __syncthreads();

        float scf[4][4] = {};
        #pragma unroll 16
        for (int d = 0; d < 64; d++) {
            float4 qv = *(float4*)&Qs[d*68 + qy];
            float4 kv = *(float4*)&Ks[d*68 + kx];
            float qa[4] = {qv.x,qv.y,qv.z,qv.w};
            float ka[4] = {kv.x,kv.y,kv.z,kv.w};
            #pragma unroll
            for (int i = 0; i < 4; i++)
                #pragma unroll
                for (int j = 0; j < 4; j++)
                    scf[i][j] = fmaf(qa[i], ka[j], scf[i][j]);
        }

        #pragma unroll
        for (int i = 0; i < 4; i++) {
            int qg = q0 + qy + i;
            #pragma unroll
            for (int j = 0; j < 4; j++) {
                int kg = k0 + kx + j;
                float p = 0.f;
                if (kg <= qg + 1)
                    p = __expf(scf[i][j]*0.125f + msk[kx+j]);
                lsum[i] += p;
                Ps[(kx+j)*68 + (qy+i)] = p;
            }
        }
        __syncthreads();

        #pragma unroll 16
        for (int k = 0; k < 64; k++) {
            float4 pv = *(float4*)&Ps[k*68 + qy];
            float4 vv = *(float4*)&Vs[k*68 + dx];
            float pa[4] = {pv.x,pv.y,pv.z,pv.w};
            float va[4] = {vv.x,vv.y,vv.z,vv.w};
            #pragma unroll
            for (int i = 0; i < 4; i++)
                #pragma unroll
                for (int j = 0; j < 4; j++)
                    o[i][j] = fmaf(pa[i], va[j], o[i][j]);
        }
    }

    __syncthreads();
    #pragma unroll
    for (int i = 0; i < 4; i++) red[(qy+i)*17 + tx] = lsum[i];
    __syncthreads();

    float* AOg = g_AO + (size_t)b_*SC*EMBEDC + h*HDIMC;
    #pragma unroll
    for (int i = 0; i < 4; i++) {
        int s = q0 + qy + i;
        if (s >= SC) continue;
        float t = 0.f;
        #pragma unroll
        for (int r = 0; r < 16; r++) t += red[(qy+i)*17 + r];
        float inv = 1.f / t;
        float4 ov = make_float4(o[i][0]*inv, o[i][1]*inv, o[i][2]*inv, o[i][3]*inv);
        *(float4*)(AOg + (size_t)s*EMBEDC + dx) = ov;
    }
}

// ---------------------------------------------------------------------------
// Kernel 4: out = g_AO @ c_proj_w + c_proj_b  (same SGEMM shape, N=1024)
// ---------------------------------------------------------------------------
__global__ __launch_bounds__(256) void k_proj(const float* __restrict__ W,
                                              const float* __restrict__ bias,
                                              float* __restrict__ C)
{
    __shared__ __align__(16) float As[16*132];
    __shared__ __align__(16) float Bs[16*132];
    const int tid = threadIdx.x;
    const int bm = blockIdx.y * 128;
    const int bn = blockIdx.x * 128;
    const int tm = (tid >> 4) * 8;
    const int tn = (tid & 15) * 8;
    float acc[8][8] = {};
    const float* A = g_AO;

    for (int kt = 0; kt < 1024; kt += 16) {
        #pragma unroll
        for (int i = 0; i < 2; i++) {
            int f = tid + i*256;
            int r = f >> 2, c = (f & 3) << 2;
            int gr = bm + r;
            float4 v = make_float4(0.f,0.f,0.f,0.f);
            if (gr < M1) v = *(const float4*)(A + (size_t)gr*1024 + kt + c);
            As[(c+0)*132 + r] = v.x;
            As[(c+1)*132 + r] = v.y;
            As[(c+2)*132 + r] = v.z;
            As[(c+3)*132 + r] = v.w;
        }
        #pragma unroll
        for (int i = 0; i < 2; i++) {
            int f = tid + i*256;
            int r = f >> 5, c = (f & 31) << 2;
            *(float4*)&Bs[r*132 + c] =
                *(const float4*)(W + (size_t)(kt+r)*1024 + bn + c);
        }
        __syncthreads();
        #pragma unroll
        for (int k = 0; k < 16; k++) {
            float av[8], bv[8];
            *(float4*)&av[0] = *(float4*)&As[k*132 + tm];
            *(float4*)&av[4] = *(float4*)&As[k*132 + tm + 4];
            *(float4*)&bv[0] = *(float4*)&Bs[k*132 + tn];
            *(float4*)&bv[4] = *(float4*)&Bs[k*132 + tn + 4];
            #pragma unroll
            for (int i = 0; i < 8; i++)
                #pragma unroll
                for (int j = 0; j < 8; j++)
                    acc[i][j] = fmaf(av[i], bv[j], acc[i][j]);
        }
        __syncthreads();
    }

    const int n0 = bn + tn;
    float bb[8];
    #pragma unroll
    for (int j = 0; j < 8; j++) bb[j] = bias[n0 + j];
    #pragma unroll
    for (int i = 0; i < 8; i++) {
        int m = bm + tm + i;
        if (m >= M1) continue;
        float4 v0 = make_float4(acc[i][0]+bb[0], acc[i][1]+bb[1],
                                acc[i][2]+bb[2], acc[i][3]+bb[3]);
        float4 v1 = make_float4(acc[i][4]+bb[4], acc[i][5]+bb[5],
                                acc[i][6]+bb[6], acc[i][7]+bb[7]);
        *(float4*)(C + (size_t)m*1024 + n0)     = v0;
        *(float4*)(C + (size_t)m*1024 + n0 + 4) = v1;
    }
}

// ---------------------------------------------------------------------------
extern "C" void kernel_launch(void* const* d_in, const int* in_sizes, int n_in,
                              void* d_out, int out_size)
{
    (void)in_sizes; (void)n_in; (void)out_size;
    const float* word  = (const float*)d_in[0];
    const float* img   = (const float*)d_in[1];
    const float* amask = (const float*)d_in[2];
    const float* caw   = (const float*)d_in[3];
    const float* cab   = (const float*)d_in[4];
    const float* cpw   = (const float*)d_in[5];
    const float* cpb   = (const float*)d_in[6];
    const float* ukw   = (const float*)d_in[7];
    const float* ukb   = (const float*)d_in[8];
    const float* uvw   = (const float*)d_in[9];
    const float* uvb   = (const float*)d_in[10];
    float* out = (float*)d_out;

    const int smem_attn = (4*64*68 + 64*17 + 64) * (int)sizeof(float); // 74240 B
    cudaFuncSetAttribute(k_attn, cudaFuncAttributeMaxDynamicSharedMemorySize,
                         smem_attn);

    dim3 g1(24, 32);
    k_qkv<<<g1, 256>>>(word, caw, cab);

    k_img<<<1024, 256>>>(img, ukw, ukb, uvw, uvb);

    dim3 ga(16, 16, 4);
    k_attn<<<ga, 256, smem_attn>>>(amask);

    dim3 g2(8, 32);
    k_proj<<<g2, 256>>>(cpw, cpb, out);
}

// round 2
// speedup vs baseline: 1.6854x; 1.6854x over previous
#include <cuda_runtime.h>

#define EMBEDC 1024
#define HEADSC 16
#define HDIMC  64
#define BC     4
#define SC     1023
#define TC     1024
#define M1     (BC*SC)   // 4092

// Scratch (allocation-free rule: __device__ globals)
__device__ float g_Q[BC*HEADSC*SC*HDIMC];   // [b][h][s][d]
__device__ float g_K[BC*HEADSC*TC*HDIMC];   // [b][h][t][d], t=0 is image token
__device__ float g_V[BC*HEADSC*TC*HDIMC];
__device__ float g_AO[BC*SC*EMBEDC];        // attention output, (B,S,E)

__device__ __forceinline__ unsigned f2tf(float x) {
    unsigned r;
    asm("cvt.rna.tf32.f32 %0, %1;" : "=r"(r) : "f"(x));
    return r;
}

__device__ __forceinline__ void mma_tf32(float c[4], const unsigned a[4],
                                         const unsigned b[2]) {
    asm volatile(
        "mma.sync.aligned.m16n8k8.row.col.f32.tf32.tf32.f32 "
        "{%0,%1,%2,%3}, {%4,%5,%6,%7}, {%8,%9}, {%0,%1,%2,%3};"
        : "+f"(c[0]), "+f"(c[1]), "+f"(c[2]), "+f"(c[3])
        : "r"(a[0]), "r"(a[1]), "r"(a[2]), "r"(a[3]), "r"(b[0]), "r"(b[1]));
}

// ---------------------------------------------------------------------------
// tf32 tensor-core GEMM: C[128x128 tile] = A[M1 x 1024] * W[1024 x NW] + bias
// 256 threads = 8 warps (2x4), warp tile 64x32, K chunk 16 per smem stage.
// Smem bank-perfect fragment loads: As stride 20 (=4 mod 32), Bs stride 132.
// ---------------------------------------------------------------------------
#define AS_STRIDE 20
#define BS_STRIDE 132

// Epilogue mode 0: scatter qkv into g_Q/g_K/g_V (NW=3072)
// Epilogue mode 1: plain store + bias into C (NW=1024)
template<int NW, int MODE>
__global__ __launch_bounds__(256) void k_gemm_tf32(const float* __restrict__ A,
                                                   const float* __restrict__ W,
                                                   const float* __restrict__ bias,
                                                   float* __restrict__ C)
{
    __shared__ __align__(16) unsigned As[128*AS_STRIDE];  // [m][k] k-chunk 16
    __shared__ __align__(16) unsigned Bs[16*BS_STRIDE];   // [k][n] 128 wide

    const int tid = threadIdx.x;
    const int bm = blockIdx.y * 128;
    const int bn = blockIdx.x * 128;
    const int wid = tid >> 5, lane = tid & 31;
    const int wm = wid >> 2, wn = wid & 3;       // 2 x 4 warps
    const int rq = lane >> 2, cq = lane & 3;

    // gmem load indices
    const int ar = tid >> 2, ac = (tid & 3) << 2;     // A: f = tid + i*256
    const int br = tid >> 5, bc = (tid & 31) << 2;    // B

    float acc[4][4][4] = {};

    for (int kt = 0; kt < 1024; kt += 16) {
        // ---- load tile to regs ----
        unsigned av[2][4], bv[2][4];
        #pragma unroll
        for (int i = 0; i < 2; i++) {
            int r = ar + i*64;
            int gr = bm + r;
            float4 v = make_float4(0.f,0.f,0.f,0.f);
            if (gr < M1) v = *(const float4*)(A + (size_t)gr*1024 + kt + ac);
            av[i][0] = f2tf(v.x); av[i][1] = f2tf(v.y);
            av[i][2] = f2tf(v.z); av[i][3] = f2tf(v.w);
        }
        #pragma unroll
        for (int i = 0; i < 2; i++) {
            int r = br + i*8;
            float4 v = *(const float4*)(W + (size_t)(kt+r)*NW + bn + bc);
            bv[i][0] = f2tf(v.x); bv[i][1] = f2tf(v.y);
            bv[i][2] = f2tf(v.z); bv[i][3] = f2tf(v.w);
        }
        __syncthreads();   // previous compute done
        #pragma unroll
        for (int i = 0; i < 2; i++) {
            int r = ar + i*64;
            *(uint4*)&As[r*AS_STRIDE + ac] =
                make_uint4(av[i][0], av[i][1], av[i][2], av[i][3]);
        }
        #pragma unroll
        for (int i = 0; i < 2; i++) {
            int r = br + i*8;
            *(uint4*)&Bs[r*BS_STRIDE + bc] =
                make_uint4(bv[i][0], bv[i][1], bv[i][2], bv[i][3]);
        }
        __syncthreads();

        // ---- compute 2 k8 chunks ----
        #pragma unroll
        for (int k0 = 0; k0 < 16; k0 += 8) {
            unsigned af[4][4], bf[4][2];
            #pragma unroll
            for (int mt = 0; mt < 4; mt++) {
                int row = wm*64 + mt*16 + rq;
                af[mt][0] = As[(row  )*AS_STRIDE + k0 + cq];
                af[mt][1] = As[(row+8)*AS_STRIDE + k0 + cq];
                af[mt][2] = As[(row  )*AS_STRIDE + k0 + cq + 4];
                af[mt][3] = As[(row+8)*AS_STRIDE + k0 + cq + 4];
            }
            #pragma unroll
            for (int nt = 0; nt < 4; nt++) {
                int col = wn*32 + nt*8 + rq;
                bf[nt][0] = Bs[(k0 + cq    )*BS_STRIDE + col];
                bf[nt][1] = Bs[(k0 + cq + 4)*BS_STRIDE + col];
            }
            #pragma unroll
            for (int mt = 0; mt < 4; mt++)
                #pragma unroll
                for (int nt = 0; nt < 4; nt++)
                    mma_tf32(acc[mt][nt], af[mt], bf[nt]);
        }
    }

    // ---- epilogue ----
    #pragma unroll
    for (int nt = 0; nt < 4; nt++) {
        const int gc = bn + wn*32 + nt*8 + 2*cq;
        const float b0 = bias[gc], b1 = bias[gc+1];
        int region = 0, h, d0;
        if (MODE == 0) {
            region = gc >> 10;
            int w0 = gc & 1023;
            h = w0 >> 6; d0 = w0 & 63;
        }
        #pragma unroll
        for (int mt = 0; mt < 4; mt++) {
            #pragma unroll
            for (int half = 0; half < 2; half++) {
                int row = bm + wm*64 + mt*16 + rq + 8*half;
                if (row >= M1) continue;
                float2 v = make_float2(acc[mt][nt][2*half]   + b0,
                                       acc[mt][nt][2*half+1] + b1);
                if (MODE == 0) {
                    int b_ = row / SC;
                    int s  = row - b_ * SC;
                    float* dst; size_t idx;
                    if (region == 0) {
                        dst = g_Q; idx = (((size_t)b_*HEADSC + h)*SC + s)*HDIMC + d0;
                    } else if (region == 1) {
                        dst = g_K; idx = (((size_t)b_*HEADSC + h)*TC + (s+1))*HDIMC + d0;
                    } else {
                        dst = g_V; idx = (((size_t)b_*HEADSC + h)*TC + (s+1))*HDIMC + d0;
                    }
                    *(float2*)(dst + idx) = v;
                } else {
                    *(float2*)(C + (size_t)row*NW + gc) = v;
                }
            }
        }
    }
}

// ---------------------------------------------------------------------------
// Kernel 2: image token K/V:  k_img[b][j] = img[b]·uk_w[j,:] + uk_b[j]
// ---------------------------------------------------------------------------
__global__ __launch_bounds__(256) void k_img(const float* __restrict__ img,
                                             const float* __restrict__ ukw,
                                             const float* __restrict__ ukb,
                                             const float* __restrict__ uvw,
                                             const float* __restrict__ uvb)
{
    int gw   = (blockIdx.x * blockDim.x + threadIdx.x) >> 5;
    int lane = threadIdx.x & 31;
    int which = gw >> 12;          // 0 -> K, 1 -> V
    int rem = gw & 4095;
    int b_ = rem >> 10;
    int j  = rem & 1023;
    const float* w  = which ? uvw : ukw;
    const float* bb = which ? uvb : ukb;

    const float4* x4 = (const float4*)(img + (size_t)b_*1024);
    const float4* w4 = (const float4*)(w + (size_t)j*1024);
    float s = 0.f;
    for (int e = lane; e < 256; e += 32) {
        float4 a = x4[e], b = w4[e];
        s += a.x*b.x + a.y*b.y + a.z*b.z + a.w*b.w;
    }
    #pragma unroll
    for (int o = 16; o; o >>= 1) s += __shfl_xor_sync(0xffffffffu, s, o);
    if (lane == 0) {
        int h = j >> 6, d = j & 63;
        float* dst = which ? g_V : g_K;
        dst[(((size_t)b_*HEADSC + h)*TC + 0)*HDIMC + d] = s + bb[j];
    }
}

// ---------------------------------------------------------------------------
// Kernel 3: attention (unchanged FFMA version this round).
// ---------------------------------------------------------------------------
__global__ __launch_bounds__(256) void k_attn(const float* __restrict__ amask)
{
    extern __shared__ __align__(16) float sm[];
    float* Qs  = sm;                 // [d][q]  64 x 68
    float* Ks  = Qs + 64*68;         // [d][k]  64 x 68
    float* Vs  = Ks + 64*68;         // [k][d]  64 x 68
    float* Ps  = Vs + 64*68;         // [k][q]  64 x 68
    float* red = Ps + 64*68;         // 64 x 17
    float* msk = red + 64*17;        // 64

    const int tid = threadIdx.x;
    const int qt = blockIdx.x, h = blockIdx.y, b_ = blockIdx.z;
    const int q0 = qt * 64;
    const float* Qg = g_Q + (((size_t)b_*HEADSC + h)*SC) * HDIMC;
    const float* Kg = g_K + (((size_t)b_*HEADSC + h)*TC) * HDIMC;
    const float* Vg = g_V + (((size_t)b_*HEADSC + h)*TC) * HDIMC;

    #pragma unroll
    for (int i = 0; i < 4; i++) {                // load Q tile transposed
        int f = tid + i*256;
        int q = f >> 4, c = (f & 15) << 2;
        int gq = q0 + q;
        float4 v = make_float4(0.f,0.f,0.f,0.f);
        if (gq < SC) v = *(const float4*)(Qg + (size_t)gq*HDIMC + c);
        Qs[(c+0)*68 + q] = v.x;
        Qs[(c+1)*68 + q] = v.y;
        Qs[(c+2)*68 + q] = v.z;
        Qs[(c+3)*68 + q] = v.w;
    }

    const int ty = tid >> 4, tx = tid & 15;
    const int qy = ty * 4, kx = tx * 4, dx = tx * 4;
    float o[4][4] = {};
    float lsum[4] = {0.f,0.f,0.f,0.f};

    const int kmax = min(TC - 1, q0 + 64);   // last valid key index
    const int nkt  = (kmax >> 6) + 1;

    for (int kt = 0; kt < nkt; kt++) {
        const int k0 = kt * 64;
        __syncthreads();                       // protect Ks/Vs/Ps from prev iter
        #pragma unroll
        for (int i = 0; i < 4; i++) {
            int f = tid + i*256;
            int kk = f >> 4, c = (f & 15) << 2;
            float4 v = *(const float4*)(Kg + (size_t)(k0+kk)*HDIMC + c);
            Ks[(c+0)*68 + kk] = v.x;
            Ks[(c+1)*68 + kk] = v.y;
            Ks[(c+2)*68 + kk] = v.z;
            Ks[(c+3)*68 + kk] = v.w;
            *(float4*)&Vs[kk*68 + c] = *(const float4*)(Vg + (size_t)(k0+kk)*HDIMC + c);
        }
        if (tid < 64) {
            int j = k0 + tid;
            msk[tid] = (j == 0) ? 0.f : amask[(size_t)b_*SC + j - 1];
        }
        __syncthreads();

        float scf[4][4] = {};
        #pragma unroll 16
        for (int d = 0; d < 64; d++) {
            float4 qv = *(float4*)&Qs[d*68 + qy];
            float4 kv = *(float4*)&Ks[d*68 + kx];
            float qa[4] = {qv.x,qv.y,qv.z,qv.w};
            float ka[4] = {kv.x,kv.y,kv.z,kv.w};
            #pragma unroll
            for (int i = 0; i < 4; i++)
                #pragma unroll
                for (int j = 0; j < 4; j++)
                    scf[i][j] = fmaf(qa[i], ka[j], scf[i][j]);
        }

        #pragma unroll
        for (int i = 0; i < 4; i++) {
            int qg = q0 + qy + i;
            #pragma unroll
            for (int j = 0; j < 4; j++) {
                int kg = k0 + kx + j;
                float p = 0.f;
                if (kg <= qg + 1)
                    p = __expf(scf[i][j]*0.125f + msk[kx+j]);
                lsum[i] += p;
                Ps[(kx+j)*68 + (qy+i)] = p;
            }
        }
        __syncthreads();

        #pragma unroll 16
        for (int k = 0; k < 64; k++) {
            float4 pv = *(float4*)&Ps[k*68 + qy];
            float4 vv = *(float4*)&Vs[k*68 + dx];
            float pa[4] = {pv.x,pv.y,pv.z,pv.w};
            float va[4] = {vv.x,vv.y,vv.z,vv.w};
            #pragma unroll
            for (int i = 0; i < 4; i++)
                #pragma unroll
                for (int j = 0; j < 4; j++)
                    o[i][j] = fmaf(pa[i], va[j], o[i][j]);
        }
    }

    __syncthreads();
    #pragma unroll
    for (int i = 0; i < 4; i++) red[(qy+i)*17 + tx] = lsum[i];
    __syncthreads();

    float* AOg = g_AO + (size_t)b_*SC*EMBEDC + h*HDIMC;
    #pragma unroll
    for (int i = 0; i < 4; i++) {
        int s = q0 + qy + i;
        if (s >= SC) continue;
        float t = 0.f;
        #pragma unroll
        for (int r = 0; r < 16; r++) t += red[(qy+i)*17 + r];
        float inv = 1.f / t;
        float4 ov = make_float4(o[i][0]*inv, o[i][1]*inv, o[i][2]*inv, o[i][3]*inv);
        *(float4*)(AOg + (size_t)s*EMBEDC + dx) = ov;
    }
}

// ---------------------------------------------------------------------------
extern "C" void kernel_launch(void* const* d_in, const int* in_sizes, int n_in,
                              void* d_out, int out_size)
{
    (void)in_sizes; (void)n_in; (void)out_size;
    const float* word  = (const float*)d_in[0];
    const float* img   = (const float*)d_in[1];
    const float* amask = (const float*)d_in[2];
    const float* caw   = (const float*)d_in[3];
    const float* cab   = (const float*)d_in[4];
    const float* cpw   = (const float*)d_in[5];
    const float* cpb   = (const float*)d_in[6];
    const float* ukw   = (const float*)d_in[7];
    const float* ukb   = (const float*)d_in[8];
    const float* uvw   = (const float*)d_in[9];
    const float* uvb   = (const float*)d_in[10];
    float* out = (float*)d_out;

    const int smem_attn = (4*64*68 + 64*17 + 64) * (int)sizeof(float); // 74240 B
    cudaFuncSetAttribute(k_attn, cudaFuncAttributeMaxDynamicSharedMemorySize,
                         smem_attn);

    dim3 g1(24, 32);
    k_gemm_tf32<3072, 0><<<g1, 256>>>(word, caw, cab, nullptr);

    k_img<<<1024, 256>>>(img, ukw, ukb, uvw, uvb);

    dim3 ga(16, 16, 4);
    k_attn<<<ga, 256, smem_attn>>>(amask);

    float* ao;
    cudaGetSymbolAddress((void**)&ao, g_AO);
    dim3 g2(8, 32);
    k_gemm_tf32<1024, 1><<<g2, 256>>>(ao, cpw, cpb, out);
}

// round 3
// speedup vs baseline: 2.3201x; 1.3767x over previous
#include <cuda_runtime.h>

#define EMBEDC 1024
#define HEADSC 16
#define HDIMC  64
#define BC     4
#define SC     1023
#define TC     1024
#define M1     (BC*SC)   // 4092

// Scratch (allocation-free rule: __device__ globals)
__device__ float g_Q[BC*HEADSC*SC*HDIMC];   // [b][h][s][d]
__device__ float g_K[BC*HEADSC*TC*HDIMC];   // [b][h][t][d], t=0 is image token
__device__ float g_V[BC*HEADSC*TC*HDIMC];
__device__ float g_AO[BC*SC*EMBEDC];        // attention output, (B,S,E)

__device__ __forceinline__ unsigned f2tf(float x) {
    unsigned r;
    asm("cvt.rna.tf32.f32 %0, %1;" : "=r"(r) : "f"(x));
    return r;
}

__device__ __forceinline__ void mma_tf32(float c[4], const unsigned a[4],
                                         const unsigned b[2]) {
    asm volatile(
        "mma.sync.aligned.m16n8k8.row.col.f32.tf32.tf32.f32 "
        "{%0,%1,%2,%3}, {%4,%5,%6,%7}, {%8,%9}, {%0,%1,%2,%3};"
        : "+f"(c[0]), "+f"(c[1]), "+f"(c[2]), "+f"(c[3])
        : "r"(a[0]), "r"(a[1]), "r"(a[2]), "r"(a[3]), "r"(b[0]), "r"(b[1]));
}

// ---------------------------------------------------------------------------
// tf32 GEMM, double-buffered smem, 1 sync per K16 step.
// A-side stride 20 (=4 mod 32), B-side stride 136 (=8 mod 32): both fragment
// load patterns hit all 32 banks.
// ---------------------------------------------------------------------------
#define AS_STRIDE 20
#define BS_STRIDE 136

template<int NW, int MODE>
__global__ __launch_bounds__(256) void k_gemm_tf32(const float* __restrict__ A,
                                                   const float* __restrict__ W,
                                                   const float* __restrict__ bias,
                                                   float* __restrict__ C)
{
    __shared__ __align__(16) unsigned As[2][128*AS_STRIDE];
    __shared__ __align__(16) unsigned Bs[2][16*BS_STRIDE];

    const int tid = threadIdx.x;
    const int bm = blockIdx.y * 128;
    const int bn = blockIdx.x * 128;
    const int wid = tid >> 5, lane = tid & 31;
    const int wm = wid >> 2, wn = wid & 3;       // 2 x 4 warps
    const int rq = lane >> 2, cq = lane & 3;

    const int ar = tid >> 2, ac = (tid & 3) << 2;
    const int br = tid >> 5, bc = (tid & 31) << 2;

    float acc[4][4][4] = {};
    unsigned av[2][4], bv[2][4];

#define LOADR(KT) do {                                                        \
        int kof = (KT) * 16;                                                  \
        _Pragma("unroll")                                                     \
        for (int i = 0; i < 2; i++) {                                         \
            int gr = bm + ar + i*64;                                          \
            float4 v = make_float4(0.f,0.f,0.f,0.f);                          \
            if (gr < M1) v = *(const float4*)(A + (size_t)gr*1024 + kof + ac);\
            av[i][0] = f2tf(v.x); av[i][1] = f2tf(v.y);                       \
            av[i][2] = f2tf(v.z); av[i][3] = f2tf(v.w);                       \
        }                                                                     \
        _Pragma("unroll")                                                     \
        for (int i = 0; i < 2; i++) {                                         \
            int r = br + i*8;                                                 \
            float4 v = *(const float4*)(W + (size_t)(kof+r)*NW + bn + bc);    \
            bv[i][0] = f2tf(v.x); bv[i][1] = f2tf(v.y);                       \
            bv[i][2] = f2tf(v.z); bv[i][3] = f2tf(v.w);                       \
        }                                                                     \
    } while(0)

#define STORES(BUF) do {                                                      \
        _Pragma("unroll")                                                     \
        for (int i = 0; i < 2; i++)                                           \
            *(uint4*)&As[BUF][(ar + i*64)*AS_STRIDE + ac] =                   \
                make_uint4(av[i][0], av[i][1], av[i][2], av[i][3]);           \
        _Pragma("unroll")                                                     \
        for (int i = 0; i < 2; i++)                                           \
            *(uint4*)&Bs[BUF][(br + i*8)*BS_STRIDE + bc] =                    \
                make_uint4(bv[i][0], bv[i][1], bv[i][2], bv[i][3]);           \
    } while(0)

    LOADR(0);
    STORES(0);
    LOADR(1);
    __syncthreads();

    for (int kt = 0; kt < 64; kt++) {
        const int cur = kt & 1;
        if (kt + 1 < 64) STORES(cur ^ 1);

        #pragma unroll
        for (int k0 = 0; k0 < 16; k0 += 8) {
            unsigned af[4][4], bf[4][2];
            #pragma unroll
            for (int mt = 0; mt < 4; mt++) {
                int row = wm*64 + mt*16 + rq;
                af[mt][0] = As[cur][(row  )*AS_STRIDE + k0 + cq];
                af[mt][1] = As[cur][(row+8)*AS_STRIDE + k0 + cq];
                af[mt][2] = As[cur][(row  )*AS_STRIDE + k0 + cq + 4];
                af[mt][3] = As[cur][(row+8)*AS_STRIDE + k0 + cq + 4];
            }
            #pragma unroll
            for (int nt = 0; nt < 4; nt++) {
                int col = wn*32 + nt*8 + rq;
                bf[nt][0] = Bs[cur][(k0 + cq    )*BS_STRIDE + col];
                bf[nt][1] = Bs[cur][(k0 + cq + 4)*BS_STRIDE + col];
            }
            #pragma unroll
            for (int mt = 0; mt < 4; mt++)
                #pragma unroll
                for (int nt = 0; nt < 4; nt++)
                    mma_tf32(acc[mt][nt], af[mt], bf[nt]);
        }
        __syncthreads();
        if (kt + 2 < 64) LOADR(kt + 2);
    }
#undef LOADR
#undef STORES

    // ---- epilogue ----
    #pragma unroll
    for (int nt = 0; nt < 4; nt++) {
        const int gc = bn + wn*32 + nt*8 + 2*cq;
        const float b0 = bias[gc], b1 = bias[gc+1];
        int region = 0, h, d0;
        if (MODE == 0) {
            region = gc >> 10;
            int w0 = gc & 1023;
            h = w0 >> 6; d0 = w0 & 63;
        }
        #pragma unroll
        for (int mt = 0; mt < 4; mt++) {
            #pragma unroll
            for (int half = 0; half < 2; half++) {
                int row = bm + wm*64 + mt*16 + rq + 8*half;
                if (row >= M1) continue;
                float2 v = make_float2(acc[mt][nt][2*half]   + b0,
                                       acc[mt][nt][2*half+1] + b1);
                if (MODE == 0) {
                    int b_ = row / SC;
                    int s  = row - b_ * SC;
                    float* dst; size_t idx;
                    if (region == 0) {
                        dst = g_Q; idx = (((size_t)b_*HEADSC + h)*SC + s)*HDIMC + d0;
                    } else if (region == 1) {
                        dst = g_K; idx = (((size_t)b_*HEADSC + h)*TC + (s+1))*HDIMC + d0;
                    } else {
                        dst = g_V; idx = (((size_t)b_*HEADSC + h)*TC + (s+1))*HDIMC + d0;
                    }
                    *(float2*)(dst + idx) = v;
                } else {
                    *(float2*)(C + (size_t)row*NW + gc) = v;
                }
            }
        }
    }
}

// ---------------------------------------------------------------------------
// Kernel 2: image token K/V (unchanged).
// ---------------------------------------------------------------------------
__global__ __launch_bounds__(256) void k_img(const float* __restrict__ img,
                                             const float* __restrict__ ukw,
                                             const float* __restrict__ ukb,
                                             const float* __restrict__ uvw,
                                             const float* __restrict__ uvb)
{
    int gw   = (blockIdx.x * blockDim.x + threadIdx.x) >> 5;
    int lane = threadIdx.x & 31;
    int which = gw >> 12;
    int rem = gw & 4095;
    int b_ = rem >> 10;
    int j  = rem & 1023;
    const float* w  = which ? uvw : ukw;
    const float* bb = which ? uvb : ukb;

    const float4* x4 = (const float4*)(img + (size_t)b_*1024);
    const float4* w4 = (const float4*)(w + (size_t)j*1024);
    float s = 0.f;
    for (int e = lane; e < 256; e += 32) {
        float4 a = x4[e], b = w4[e];
        s += a.x*b.x + a.y*b.y + a.z*b.z + a.w*b.w;
    }
    #pragma unroll
    for (int o = 16; o; o >>= 1) s += __shfl_xor_sync(0xffffffffu, s, o);
    if (lane == 0) {
        int h = j >> 6, d = j & 63;
        float* dst = which ? g_V : g_K;
        dst[(((size_t)b_*HEADSC + h)*TC + 0)*HDIMC + d] = s + bb[j];
    }
}

// ---------------------------------------------------------------------------
// Kernel 3: tensor-core attention. Block = (qt, h, b); 64 queries.
// Warp grid 4x2: wm = query 16-block, wn = key/d 32-half.
// Strides: A-side (Qs, Ps) 68 (=4 mod 32); B-side (Ks, Vs) 72 (=8 mod 32).
// ---------------------------------------------------------------------------
#define SQ 68
#define SKV 72

__global__ __launch_bounds__(256) void k_attn(const float* __restrict__ amask)
{
    extern __shared__ __align__(16) unsigned smu[];
    unsigned* Qs = smu;               // [q][d] tf32
    unsigned* Ks = Qs + 64*SQ;        // [d][k] tf32
    unsigned* Vs = Ks + 64*SKV;       // [k][d] tf32
    unsigned* Ps = Vs + 64*SKV;       // [q][k] tf32
    float* red = (float*)(Ps + 64*SQ);   // [2][64]
    float* msk = red + 128;              // [64]

    const int tid = threadIdx.x;
    const int qt = blockIdx.x, h = blockIdx.y, b_ = blockIdx.z;
    const int q0 = qt * 64;
    const float* Qg = g_Q + (((size_t)b_*HEADSC + h)*SC) * HDIMC;
    const float* Kg = g_K + (((size_t)b_*HEADSC + h)*TC) * HDIMC;
    const float* Vg = g_V + (((size_t)b_*HEADSC + h)*TC) * HDIMC;

    // load Q tile -> Qs[q][d] as tf32
    #pragma unroll
    for (int i = 0; i < 4; i++) {
        int f = tid + i*256;
        int q = f >> 4, c = (f & 15) << 2;
        int gq = q0 + q;
        float4 v = make_float4(0.f,0.f,0.f,0.f);
        if (gq < SC) v = *(const float4*)(Qg + (size_t)gq*HDIMC + c);
        *(uint4*)&Qs[q*SQ + c] = make_uint4(f2tf(v.x), f2tf(v.y),
                                            f2tf(v.z), f2tf(v.w));
    }

    const int wid = tid >> 5, lane = tid & 31;
    const int wm = wid >> 1, wn = wid & 1;    // 4 x 2 warps
    const int rq = lane >> 2, cq = lane & 3;
    const int row0 = wm*16 + rq;

    float o[4][4] = {};
    float lsum[2] = {0.f, 0.f};

    const int nkt = min(qt + 2, 16);

    for (int kt = 0; kt < nkt; kt++) {
        const int k0 = kt * 64;
        __syncthreads();    // prev iter's PV reads of Ks/Vs/Ps done
        #pragma unroll
        for (int i = 0; i < 4; i++) {
            int f = tid + i*256;
            int kk = f >> 4, c = (f & 15) << 2;
            float4 kv = *(const float4*)(Kg + (size_t)(k0+kk)*HDIMC + c);
            Ks[(c+0)*SKV + kk] = f2tf(kv.x);
            Ks[(c+1)*SKV + kk] = f2tf(kv.y);
            Ks[(c+2)*SKV + kk] = f2tf(kv.z);
            Ks[(c+3)*SKV + kk] = f2tf(kv.w);
            float4 vv = *(const float4*)(Vg + (size_t)(k0+kk)*HDIMC + c);
            *(uint4*)&Vs[kk*SKV + c] = make_uint4(f2tf(vv.x), f2tf(vv.y),
                                                  f2tf(vv.z), f2tf(vv.w));
        }
        if (tid < 64) {
            int j = k0 + tid;
            msk[tid] = (j == 0) ? 0.f : amask[(size_t)b_*SC + j - 1];
        }
        __syncthreads();

        // S = Q K^T  (m16 x n32 per warp)
        float s_[4][4] = {};
        #pragma unroll
        for (int kc = 0; kc < 64; kc += 8) {
            unsigned af[4];
            af[0] = Qs[(row0  )*SQ + kc + cq];
            af[1] = Qs[(row0+8)*SQ + kc + cq];
            af[2] = Qs[(row0  )*SQ + kc + cq + 4];
            af[3] = Qs[(row0+8)*SQ + kc + cq + 4];
            #pragma unroll
            for (int nt = 0; nt < 4; nt++) {
                int col = wn*32 + nt*8 + rq;
                unsigned bf[2] = { Ks[(kc + cq    )*SKV + col],
                                   Ks[(kc + cq + 4)*SKV + col] };
                mma_tf32(s_[nt], af, bf);
            }
        }

        // exp + causal mask, P -> smem (tf32)
        const int gq0 = q0 + row0;
        #pragma unroll
        for (int nt = 0; nt < 4; nt++) {
            int lc = wn*32 + nt*8 + 2*cq;
            int gc = k0 + lc;
            float m0 = msk[lc], m1 = msk[lc+1];
            float p00 = (gc     <= gq0+1) ? __expf(s_[nt][0]*0.125f + m0) : 0.f;
            float p01 = (gc + 1 <= gq0+1) ? __expf(s_[nt][1]*0.125f + m1) : 0.f;
            float p10 = (gc     <= gq0+9) ? __expf(s_[nt][2]*0.125f + m0) : 0.f;
            float p11 = (gc + 1 <= gq0+9) ? __expf(s_[nt][3]*0.125f + m1) : 0.f;
            lsum[0] += p00 + p01;
            lsum[1] += p10 + p11;
            Ps[(row0  )*SQ + lc    ] = f2tf(p00);
            Ps[(row0  )*SQ + lc + 1] = f2tf(p01);
            Ps[(row0+8)*SQ + lc    ] = f2tf(p10);
            Ps[(row0+8)*SQ + lc + 1] = f2tf(p11);
        }
        __syncthreads();

        // O += P V  (m16 x n32 per warp over d)
        #pragma unroll
        for (int kc = 0; kc < 64; kc += 8) {
            unsigned af[4];
            af[0] = Ps[(row0  )*SQ + kc + cq];
            af[1] = Ps[(row0+8)*SQ + kc + cq];
            af[2] = Ps[(row0  )*SQ + kc + cq + 4];
            af[3] = Ps[(row0+8)*SQ + kc + cq + 4];
            #pragma unroll
            for (int nt = 0; nt < 4; nt++) {
                int col = wn*32 + nt*8 + rq;
                unsigned bf[2] = { Vs[(kc + cq    )*SKV + col],
                                   Vs[(kc + cq + 4)*SKV + col] };
                mma_tf32(o[nt], af, bf);
            }
        }
    }

    // row-sum reduction: over cq quad, then across wn halves via smem
    #pragma unroll
    for (int i = 0; i < 2; i++) {
        lsum[i] += __shfl_xor_sync(0xffffffffu, lsum[i], 1);
        lsum[i] += __shfl_xor_sync(0xffffffffu, lsum[i], 2);
    }
    __syncthreads();
    if (cq == 0) {
        red[wn*64 + row0    ] = lsum[0];
        red[wn*64 + row0 + 8] = lsum[1];
    }
    __syncthreads();
    const float inv0 = 1.f / (red[row0    ] + red[64 + row0    ]);
    const float inv1 = 1.f / (red[row0 + 8] + red[64 + row0 + 8]);

    float* AOg = g_AO + (size_t)b_*SC*EMBEDC + h*HDIMC;
    const int s0 = q0 + row0;
    #pragma unroll
    for (int nt = 0; nt < 4; nt++) {
        int d = wn*32 + nt*8 + 2*cq;
        if (s0 < SC)
            *(float2*)(AOg + (size_t)s0*EMBEDC + d) =
                make_float2(o[nt][0]*inv0, o[nt][1]*inv0);
        if (s0 + 8 < SC)
            *(float2*)(AOg + (size_t)(s0+8)*EMBEDC + d) =
                make_float2(o[nt][2]*inv1, o[nt][3]*inv1);
    }
}

// ---------------------------------------------------------------------------
extern "C" void kernel_launch(void* const* d_in, const int* in_sizes, int n_in,
                              void* d_out, int out_size)
{
    (void)in_sizes; (void)n_in; (void)out_size;
    const float* word  = (const float*)d_in[0];
    const float* img   = (const float*)d_in[1];
    const float* amask = (const float*)d_in[2];
    const float* caw   = (const float*)d_in[3];
    const float* cab   = (const float*)d_in[4];
    const float* cpw   = (const float*)d_in[5];
    const float* cpb   = (const float*)d_in[6];
    const float* ukw   = (const float*)d_in[7];
    const float* ukb   = (const float*)d_in[8];
    const float* uvw   = (const float*)d_in[9];
    const float* uvb   = (const float*)d_in[10];
    float* out = (float*)d_out;

    const int smem_attn = (64*SQ*2 + 64*SKV*2 + 128 + 64) * (int)sizeof(unsigned);
    cudaFuncSetAttribute(k_attn, cudaFuncAttributeMaxDynamicSharedMemorySize,
                         smem_attn);

    dim3 g1(24, 32);
    k_gemm_tf32<3072, 0><<<g1, 256>>>(word, caw, cab, nullptr);

    k_img<<<1024, 256>>>(img, ukw, ukb, uvw, uvb);

    dim3 ga(16, 16, 4);
    k_attn<<<ga, 256, smem_attn>>>(amask);

    float* ao;
    cudaGetSymbolAddress((void**)&ao, g_AO);
    dim3 g2(8, 32);
    k_gemm_tf32<1024, 1><<<g2, 256>>>(ao, cpw, cpb, out);
}

// round 4
// speedup vs baseline: 2.3257x; 1.0024x over previous
#include <cuda_runtime.h>

#define EMBEDC 1024
#define HEADSC 16
#define HDIMC  64
#define BC     4
#define SC     1023
#define TC     1024
#define M1     (BC*SC)   // 4092

// Scratch (allocation-free rule: __device__ globals)
__device__ float g_Q[BC*HEADSC*SC*HDIMC];   // [b][h][s][d]
__device__ float g_K[BC*HEADSC*TC*HDIMC];   // [b][h][t][d], t=0 is image token
__device__ float g_V[BC*HEADSC*TC*HDIMC];
__device__ float g_AO[BC*SC*EMBEDC];        // attention output, (B,S,E)

__device__ __forceinline__ unsigned f2tf(float x) {
    unsigned r;
    asm("cvt.rna.tf32.f32 %0, %1;" : "=r"(r) : "f"(x));
    return r;
}

__device__ __forceinline__ void mma_tf32(float c[4], const unsigned a[4],
                                         const unsigned b[2]) {
    asm volatile(
        "mma.sync.aligned.m16n8k8.row.col.f32.tf32.tf32.f32 "
        "{%0,%1,%2,%3}, {%4,%5,%6,%7}, {%8,%9}, {%0,%1,%2,%3};"
        : "+f"(c[0]), "+f"(c[1]), "+f"(c[2]), "+f"(c[3])
        : "r"(a[0]), "r"(a[1]), "r"(a[2]), "r"(a[3]), "r"(b[0]), "r"(b[1]));
}

// ---------------------------------------------------------------------------
// tf32 GEMM, double-buffered smem, 1 sync per K16 step.
// A-side stride 20 (=4 mod 32), B-side stride 136 (=8 mod 32): both fragment
// load patterns hit all 32 banks.
// ---------------------------------------------------------------------------
#define AS_STRIDE 20
#define BS_STRIDE 136

template<int NW, int MODE>
__global__ __launch_bounds__(256) void k_gemm_tf32(const float* __restrict__ A,
                                                   const float* __restrict__ W,
                                                   const float* __restrict__ bias,
                                                   float* __restrict__ C)
{
    __shared__ __align__(16) unsigned As[2][128*AS_STRIDE];
    __shared__ __align__(16) unsigned Bs[2][16*BS_STRIDE];

    const int tid = threadIdx.x;
    const int bm = blockIdx.y * 128;
    const int bn = blockIdx.x * 128;
    const int wid = tid >> 5, lane = tid & 31;
    const int wm = wid >> 2, wn = wid & 3;       // 2 x 4 warps
    const int rq = lane >> 2, cq = lane & 3;

    const int ar = tid >> 2, ac = (tid & 3) << 2;
    const int br = tid >> 5, bc = (tid & 31) << 2;

    float acc[4][4][4] = {};
    unsigned av[2][4], bv[2][4];

#define LOADR(KT) do {                                                        \
        int kof = (KT) * 16;                                                  \
        _Pragma("unroll")                                                     \
        for (int i = 0; i < 2; i++) {                                         \
            int gr = bm + ar + i*64;                                          \
            float4 v = make_float4(0.f,0.f,0.f,0.f);                          \
            if (gr < M1) v = *(const float4*)(A + (size_t)gr*1024 + kof + ac);\
            av[i][0] = f2tf(v.x); av[i][1] = f2tf(v.y);                       \
            av[i][2] = f2tf(v.z); av[i][3] = f2tf(v.w);                       \
        }                                                                     \
        _Pragma("unroll")                                                     \
        for (int i = 0; i < 2; i++) {                                         \
            int r = br + i*8;                                                 \
            float4 v = *(const float4*)(W + (size_t)(kof+r)*NW + bn + bc);    \
            bv[i][0] = f2tf(v.x); bv[i][1] = f2tf(v.y);                       \
            bv[i][2] = f2tf(v.z); bv[i][3] = f2tf(v.w);                       \
        }                                                                     \
    } while(0)

#define STORES(BUF) do {                                                      \
        _Pragma("unroll")                                                     \
        for (int i = 0; i < 2; i++)                                           \
            *(uint4*)&As[BUF][(ar + i*64)*AS_STRIDE + ac] =                   \
                make_uint4(av[i][0], av[i][1], av[i][2], av[i][3]);           \
        _Pragma("unroll")                                                     \
        for (int i = 0; i < 2; i++)                                           \
            *(uint4*)&Bs[BUF][(br + i*8)*BS_STRIDE + bc] =                    \
                make_uint4(bv[i][0], bv[i][1], bv[i][2], bv[i][3]);           \
    } while(0)

    LOADR(0);
    STORES(0);
    LOADR(1);
    __syncthreads();

    for (int kt = 0; kt < 64; kt++) {
        const int cur = kt & 1;
        if (kt + 1 < 64) STORES(cur ^ 1);

        #pragma unroll
        for (int k0 = 0; k0 < 16; k0 += 8) {
            unsigned af[4][4], bf[4][2];
            #pragma unroll
            for (int mt = 0; mt < 4; mt++) {
                int row = wm*64 + mt*16 + rq;
                af[mt][0] = As[cur][(row  )*AS_STRIDE + k0 + cq];
                af[mt][1] = As[cur][(row+8)*AS_STRIDE + k0 + cq];
                af[mt][2] = As[cur][(row  )*AS_STRIDE + k0 + cq + 4];
                af[mt][3] = As[cur][(row+8)*AS_STRIDE + k0 + cq + 4];
            }
            #pragma unroll
            for (int nt = 0; nt < 4; nt++) {
                int col = wn*32 + nt*8 + rq;
                bf[nt][0] = Bs[cur][(k0 + cq    )*BS_STRIDE + col];
                bf[nt][1] = Bs[cur][(k0 + cq + 4)*BS_STRIDE + col];
            }
            #pragma unroll
            for (int mt = 0; mt < 4; mt++)
                #pragma unroll
                for (int nt = 0; nt < 4; nt++)
                    mma_tf32(acc[mt][nt], af[mt], bf[nt]);
        }
        __syncthreads();
        if (kt + 2 < 64) LOADR(kt + 2);
    }
#undef LOADR
#undef STORES

    // ---- epilogue ----
    #pragma unroll
    for (int nt = 0; nt < 4; nt++) {
        const int gc = bn + wn*32 + nt*8 + 2*cq;
        const float b0 = bias[gc], b1 = bias[gc+1];
        int region = 0, h, d0;
        if (MODE == 0) {
            region = gc >> 10;
            int w0 = gc & 1023;
            h = w0 >> 6; d0 = w0 & 63;
        }
        #pragma unroll
        for (int mt = 0; mt < 4; mt++) {
            #pragma unroll
            for (int half = 0; half < 2; half++) {
                int row = bm + wm*64 + mt*16 + rq + 8*half;
                if (row >= M1) continue;
                float2 v = make_float2(acc[mt][nt][2*half]   + b0,
                                       acc[mt][nt][2*half+1] + b1);
                if (MODE == 0) {
                    int b_ = row / SC;
                    int s  = row - b_ * SC;
                    float* dst; size_t idx;
                    if (region == 0) {
                        dst = g_Q; idx = (((size_t)b_*HEADSC + h)*SC + s)*HDIMC + d0;
                    } else if (region == 1) {
                        dst = g_K; idx = (((size_t)b_*HEADSC + h)*TC + (s+1))*HDIMC + d0;
                    } else {
                        dst = g_V; idx = (((size_t)b_*HEADSC + h)*TC + (s+1))*HDIMC + d0;
                    }
                    *(float2*)(dst + idx) = v;
                } else {
                    *(float2*)(C + (size_t)row*NW + gc) = v;
                }
            }
        }
    }
}

// ---------------------------------------------------------------------------
// Kernel 2: image token K/V (unchanged).
// ---------------------------------------------------------------------------
__global__ __launch_bounds__(256) void k_img(const float* __restrict__ img,
                                             const float* __restrict__ ukw,
                                             const float* __restrict__ ukb,
                                             const float* __restrict__ uvw,
                                             const float* __restrict__ uvb)
{
    int gw   = (blockIdx.x * blockDim.x + threadIdx.x) >> 5;
    int lane = threadIdx.x & 31;
    int which = gw >> 12;
    int rem = gw & 4095;
    int b_ = rem >> 10;
    int j  = rem & 1023;
    const float* w  = which ? uvw : ukw;
    const float* bb = which ? uvb : ukb;

    const float4* x4 = (const float4*)(img + (size_t)b_*1024);
    const float4* w4 = (const float4*)(w + (size_t)j*1024);
    float s = 0.f;
    for (int e = lane; e < 256; e += 32) {
        float4 a = x4[e], b = w4[e];
        s += a.x*b.x + a.y*b.y + a.z*b.z + a.w*b.w;
    }
    #pragma unroll
    for (int o = 16; o; o >>= 1) s += __shfl_xor_sync(0xffffffffu, s, o);
    if (lane == 0) {
        int h = j >> 6, d = j & 63;
        float* dst = which ? g_V : g_K;
        dst[(((size_t)b_*HEADSC + h)*TC + 0)*HDIMC + d] = s + bb[j];
    }
}

// ---------------------------------------------------------------------------
// Kernel 3: tensor-core attention. Block = (qt, h, b); 64 queries.
// Warp grid 4x2: wm = query 16-block, wn = key/d 32-half.
// Strides: A-side (Qs, Ps) 68 (=4 mod 32); B-side (Ks, Vs) 72 (=8 mod 32).
// ---------------------------------------------------------------------------
#define SQ 68
#define SKV 72

__global__ __launch_bounds__(256) void k_attn(const float* __restrict__ amask)
{
    extern __shared__ __align__(16) unsigned smu[];
    unsigned* Qs = smu;               // [q][d] tf32
    unsigned* Ks = Qs + 64*SQ;        // [d][k] tf32
    unsigned* Vs = Ks + 64*SKV;       // [k][d] tf32
    unsigned* Ps = Vs + 64*SKV;       // [q][k] tf32
    float* red = (float*)(Ps + 64*SQ);   // [2][64]
    float* msk = red + 128;              // [64]

    const int tid = threadIdx.x;
    const int qt = blockIdx.x, h = blockIdx.y, b_ = blockIdx.z;
    const int q0 = qt * 64;
    const float* Qg = g_Q + (((size_t)b_*HEADSC + h)*SC) * HDIMC;
    const float* Kg = g_K + (((size_t)b_*HEADSC + h)*TC) * HDIMC;
    const float* Vg = g_V + (((size_t)b_*HEADSC + h)*TC) * HDIMC;

    // load Q tile -> Qs[q][d] as tf32
    #pragma unroll
    for (int i = 0; i < 4; i++) {
        int f = tid + i*256;
        int q = f >> 4, c = (f & 15) << 2;
        int gq = q0 + q;
        float4 v = make_float4(0.f,0.f,0.f,0.f);
        if (gq < SC) v = *(const float4*)(Qg + (size_t)gq*HDIMC + c);
        *(uint4*)&Qs[q*SQ + c] = make_uint4(f2tf(v.x), f2tf(v.y),
                                            f2tf(v.z), f2tf(v.w));
    }

    const int wid = tid >> 5, lane = tid & 31;
    const int wm = wid >> 1, wn = wid & 1;    // 4 x 2 warps
    const int rq = lane >> 2, cq = lane & 3;
    const int row0 = wm*16 + rq;

    float o[4][4] = {};
    float lsum[2] = {0.f, 0.f};

    const int nkt = min(qt + 2, 16);

    for (int kt = 0; kt < nkt; kt++) {
        const int k0 = kt * 64;
        __syncthreads();    // prev iter's PV reads of Ks/Vs/Ps done
        #pragma unroll
        for (int i = 0; i < 4; i++) {
            int f = tid + i*256;
            int kk = f >> 4, c = (f & 15) << 2;
            float4 kv = *(const float4*)(Kg + (size_t)(k0+kk)*HDIMC + c);
            Ks[(c+0)*SKV + kk] = f2tf(kv.x);
            Ks[(c+1)*SKV + kk] = f2tf(kv.y);
            Ks[(c+2)*SKV + kk] = f2tf(kv.z);
            Ks[(c+3)*SKV + kk] = f2tf(kv.w);
            float4 vv = *(const float4*)(Vg + (size_t)(k0+kk)*HDIMC + c);
            *(uint4*)&Vs[kk*SKV + c] = make_uint4(f2tf(vv.x), f2tf(vv.y),
                                                  f2tf(vv.z), f2tf(vv.w));
        }
        if (tid < 64) {
            int j = k0 + tid;
            msk[tid] = (j == 0) ? 0.f : amask[(size_t)b_*SC + j - 1];
        }
        __syncthreads();

        // S = Q K^T  (m16 x n32 per warp)
        float s_[4][4] = {};
        #pragma unroll
        for (int kc = 0; kc < 64; kc += 8) {
            unsigned af[4];
            af[0] = Qs[(row0  )*SQ + kc + cq];
            af[1] = Qs[(row0+8)*SQ + kc + cq];
            af[2] = Qs[(row0  )*SQ + kc + cq + 4];
            af[3] = Qs[(row0+8)*SQ + kc + cq + 4];
            #pragma unroll
            for (int nt = 0; nt < 4; nt++) {
                int col = wn*32 + nt*8 + rq;
                unsigned bf[2] = { Ks[(kc + cq    )*SKV + col],
                                   Ks[(kc + cq + 4)*SKV + col] };
                mma_tf32(s_[nt], af, bf);
            }
        }

        // exp + causal mask, P -> smem (tf32)
        const int gq0 = q0 + row0;
        #pragma unroll
        for (int nt = 0; nt < 4; nt++) {
            int lc = wn*32 + nt*8 + 2*cq;
            int gc = k0 + lc;
            float m0 = msk[lc], m1 = msk[lc+1];
            float p00 = (gc     <= gq0+1) ? __expf(s_[nt][0]*0.125f + m0) : 0.f;
            float p01 = (gc + 1 <= gq0+1) ? __expf(s_[nt][1]*0.125f + m1) : 0.f;
            float p10 = (gc     <= gq0+9) ? __expf(s_[nt][2]*0.125f + m0) : 0.f;
            float p11 = (gc + 1 <= gq0+9) ? __expf(s_[nt][3]*0.125f + m1) : 0.f;
            lsum[0] += p00 + p01;
            lsum[1] += p10 + p11;
            Ps[(row0  )*SQ + lc    ] = f2tf(p00);
            Ps[(row0  )*SQ + lc + 1] = f2tf(p01);
            Ps[(row0+8)*SQ + lc    ] = f2tf(p10);
            Ps[(row0+8)*SQ + lc + 1] = f2tf(p11);
        }
        __syncthreads();

        // O += P V  (m16 x n32 per warp over d)
        #pragma unroll
        for (int kc = 0; kc < 64; kc += 8) {
            unsigned af[4];
            af[0] = Ps[(row0  )*SQ + kc + cq];
            af[1] = Ps[(row0+8)*SQ + kc + cq];
            af[2] = Ps[(row0  )*SQ + kc + cq + 4];
            af[3] = Ps[(row0+8)*SQ + kc + cq + 4];
            #pragma unroll
            for (int nt = 0; nt < 4; nt++) {
                int col = wn*32 + nt*8 + rq;
                unsigned bf[2] = { Vs[(kc + cq    )*SKV + col],
                                   Vs[(kc + cq + 4)*SKV + col] };
                mma_tf32(o[nt], af, bf);
            }
        }
    }

    // row-sum reduction: over cq quad, then across wn halves via smem
    #pragma unroll
    for (int i = 0; i < 2; i++) {
        lsum[i] += __shfl_xor_sync(0xffffffffu, lsum[i], 1);
        lsum[i] += __shfl_xor_sync(0xffffffffu, lsum[i], 2);
    }
    __syncthreads();
    if (cq == 0) {
        red[wn*64 + row0    ] = lsum[0];
        red[wn*64 + row0 + 8] = lsum[1];
    }
    __syncthreads();
    const float inv0 = 1.f / (red[row0    ] + red[64 + row0    ]);
    const float inv1 = 1.f / (red[row0 + 8] + red[64 + row0 + 8]);

    float* AOg = g_AO + (size_t)b_*SC*EMBEDC + h*HDIMC;
    const int s0 = q0 + row0;
    #pragma unroll
    for (int nt = 0; nt < 4; nt++) {
        int d = wn*32 + nt*8 + 2*cq;
        if (s0 < SC)
            *(float2*)(AOg + (size_t)s0*EMBEDC + d) =
                make_float2(o[nt][0]*inv0, o[nt][1]*inv0);
        if (s0 + 8 < SC)
            *(float2*)(AOg + (size_t)(s0+8)*EMBEDC + d) =
                make_float2(o[nt][2]*inv1, o[nt][3]*inv1);
    }
}

// ---------------------------------------------------------------------------
extern "C" void kernel_launch(void* const* d_in, const int* in_sizes, int n_in,
                              void* d_out, int out_size)
{
    (void)in_sizes; (void)n_in; (void)out_size;
    const float* word  = (const float*)d_in[0];
    const float* img   = (const float*)d_in[1];
    const float* amask = (const float*)d_in[2];
    const float* caw   = (const float*)d_in[3];
    const float* cab   = (const float*)d_in[4];
    const float* cpw   = (const float*)d_in[5];
    const float* cpb   = (const float*)d_in[6];
    const float* ukw   = (const float*)d_in[7];
    const float* ukb   = (const float*)d_in[8];
    const float* uvw   = (const float*)d_in[9];
    const float* uvb   = (const float*)d_in[10];
    float* out = (float*)d_out;

    const int smem_attn = (64*SQ*2 + 64*SKV*2 + 128 + 64) * (int)sizeof(unsigned);
    cudaFuncSetAttribute(k_attn, cudaFuncAttributeMaxDynamicSharedMemorySize,
                         smem_attn);

    dim3 g1(24, 32);
    k_gemm_tf32<3072, 0><<<g1, 256>>>(word, caw, cab, nullptr);

    k_img<<<1024, 256>>>(img, ukw, ukb, uvw, uvb);

    dim3 ga(16, 16, 4);
    k_attn<<<ga, 256, smem_attn>>>(amask);

    float* ao;
    cudaGetSymbolAddress((void**)&ao, g_AO);
    dim3 g2(8, 32);
    k_gemm_tf32<1024, 1><<<g2, 256>>>(ao, cpw, cpb, out);
}

// round 6
// speedup vs baseline: 2.8886x; 1.2421x over previous
#include <cuda_runtime.h>
#include <cstdint>

#define EMBEDC 1024
#define HEADSC 16
#define HDIMC  64
#define BC     4
#define SC     1023
#define TC     1024
#define M1     (BC*SC)   // 4092

// Scratch (allocation-free rule: __device__ globals)
__device__ float g_Q[BC*HEADSC*SC*HDIMC];   // [b][h][s][d], tf32-rounded
__device__ float g_K[BC*HEADSC*TC*HDIMC];   // [b][h][t][d], t=0 image, rounded
__device__ float g_V[BC*HEADSC*TC*HDIMC];   // rounded
__device__ float g_AO[BC*SC*EMBEDC];        // attn out (B,S,E), rounded
__device__ float g_Atf[M1*EMBEDC];          // word, rounded
__device__ float g_Wq[EMBEDC*3*EMBEDC];     // c_attn_w, rounded (same layout)
__device__ float g_Wp[EMBEDC*EMBEDC];       // c_proj_w, rounded

__device__ __forceinline__ unsigned f2tf(float x) {
    unsigned r; asm("cvt.rna.tf32.f32 %0, %1;" : "=r"(r) : "f"(x)); return r;
}
__device__ __forceinline__ float f2tff(float x) { return __uint_as_float(f2tf(x)); }

__device__ __forceinline__ void mma_tf32(float c[4], const unsigned a[4],
                                         const unsigned b[2]) {
    asm volatile(
        "mma.sync.aligned.m16n8k8.row.col.f32.tf32.tf32.f32 "
        "{%0,%1,%2,%3}, {%4,%5,%6,%7}, {%8,%9}, {%0,%1,%2,%3};"
        : "+f"(c[0]), "+f"(c[1]), "+f"(c[2]), "+f"(c[3])
        : "r"(a[0]), "r"(a[1]), "r"(a[2]), "r"(a[3]), "r"(b[0]), "r"(b[1]));
}

__device__ __forceinline__ uint32_t smem_u32(const void* p) {
    uint32_t a;
    asm("{ .reg .u64 t; cvta.to.shared.u64 t, %1; cvt.u32.u64 %0, t; }"
        : "=r"(a) : "l"(p));
    return a;
}
#define CP16(dst, src, sz) \
    asm volatile("cp.async.cg.shared.global [%0], [%1], 16, %2;" \
                 :: "r"(dst), "l"(src), "r"((uint32_t)(sz)) : "memory")
#define CP_COMMIT() asm volatile("cp.async.commit_group;" ::: "memory")
#define CP_WAIT(n)  asm volatile("cp.async.wait_group %0;" :: "n"(n) : "memory")

// ---------------------------------------------------------------------------
// Prep: tf32 round-copy (element count multiple of 1024 floats)
// ---------------------------------------------------------------------------
__global__ __launch_bounds__(256) void k_cvt(const float4* __restrict__ in,
                                             float4* __restrict__ out)
{
    size_t i = (size_t)blockIdx.x * 256 + threadIdx.x;
    float4 v = in[i];
    out[i] = make_float4(f2tff(v.x), f2tff(v.y), f2tff(v.z), f2tff(v.w));
}

// ---------------------------------------------------------------------------
// tf32 mma.sync GEMM, 3-stage cp.async pipeline, 128x128 tile, K16 stages.
// MODE 0: qkv scatter (rounded); MODE 1: C = A*W + b (full precision out).
// ---------------------------------------------------------------------------
#define NSTG 3
#define ASW 20            // A smem stride (words), =4 mod 32
#define BSW 136           // B smem stride (words), =8 mod 32
#define A_WORDS (128*ASW)
#define B_WORDS (16*BSW)
#define STG_WORDS (A_WORDS + B_WORDS)
#define SMEM_GEMM (NSTG*STG_WORDS*4)

template<int NW, int MODE>
__global__ __launch_bounds__(256) void k_gemm(const float* __restrict__ A,
                                              const float* __restrict__ W,
                                              const float* __restrict__ bias,
                                              float* __restrict__ C)
{
    extern __shared__ __align__(16) float smf[];

    const int tid = threadIdx.x;
    const int bm = blockIdx.y * 128;
    const int bn = blockIdx.x * 128;
    const int wid = tid >> 5, lane = tid & 31;
    const int wm = wid >> 2, wn = wid & 3;       // 2 x 4 warps, 64x32 tiles
    const int rq = lane >> 2, cq = lane & 3;

    const int ar = tid >> 2, ac = (tid & 3) << 2;
    const int br = tid >> 5, bc = (tid & 31) << 2;

    float acc[4][4][4] = {};

    auto issue = [&](int kt, int s) {
        const int kof = kt * 16;
        float* Asp = smf + s*STG_WORDS;
        float* Bsp = Asp + A_WORDS;
        #pragma unroll
        for (int i = 0; i < 2; i++) {
            int r = ar + i*64;
            int gr = bm + r;
            CP16(smem_u32(Asp + r*ASW + ac),
                 A + (size_t)gr*1024 + kof + ac, (gr < M1) ? 16 : 0);
        }
        #pragma unroll
        for (int i = 0; i < 2; i++) {
            int r = br + i*8;
            CP16(smem_u32(Bsp + r*BSW + bc),
                 W + (size_t)(kof + r)*NW + bn + bc, 16);
        }
        CP_COMMIT();
    };

    issue(0, 0);
    issue(1, 1);

    int s = 0;
    for (int kt = 0; kt < 64; kt++) {
        if (kt < 63) { CP_WAIT(1); } else { CP_WAIT(0); }
        __syncthreads();
        if (kt + 2 < 64) {
            int s2 = s + 2; if (s2 >= NSTG) s2 -= NSTG;
            issue(kt + 2, s2);
        }
        const float* Asp = smf + s*STG_WORDS;
        const float* Bsp = Asp + A_WORDS;

        #pragma unroll
        for (int k0 = 0; k0 < 16; k0 += 8) {
            unsigned af[4][4], bf[4][2];
            #pragma unroll
            for (int mt = 0; mt < 4; mt++) {
                int row = wm*64 + mt*16 + rq;
                af[mt][0] = __float_as_uint(Asp[(row  )*ASW + k0 + cq]);
                af[mt][1] = __float_as_uint(Asp[(row+8)*ASW + k0 + cq]);
                af[mt][2] = __float_as_uint(Asp[(row  )*ASW + k0 + cq + 4]);
                af[mt][3] = __float_as_uint(Asp[(row+8)*ASW + k0 + cq + 4]);
            }
            #pragma unroll
            for (int nt = 0; nt < 4; nt++) {
                int col = wn*32 + nt*8 + rq;
                bf[nt][0] = __float_as_uint(Bsp[(k0 + cq    )*BSW + col]);
                bf[nt][1] = __float_as_uint(Bsp[(k0 + cq + 4)*BSW + col]);
            }
            #pragma unroll
            for (int mt = 0; mt < 4; mt++)
                #pragma unroll
                for (int nt = 0; nt < 4; nt++)
                    mma_tf32(acc[mt][nt], af[mt], bf[nt]);
        }
        __syncthreads();
        if (++s >= NSTG) s -= NSTG;
    }

    // ---- epilogue ----
    #pragma unroll
    for (int nt = 0; nt < 4; nt++) {
        const int gc = bn + wn*32 + nt*8 + 2*cq;
        const float b0 = bias[gc], b1 = bias[gc+1];
        int region = 0, h = 0, d0 = 0;
        if (MODE == 0) {
            region = gc >> 10;
            int w0 = gc & 1023;
            h = w0 >> 6; d0 = w0 & 63;
        }
        #pragma unroll
        for (int mt = 0; mt < 4; mt++) {
            #pragma unroll
            for (int half = 0; half < 2; half++) {
                int row = bm + wm*64 + mt*16 + rq + 8*half;
                if (row >= M1) continue;
                float x0 = acc[mt][nt][2*half]   + b0;
                float x1 = acc[mt][nt][2*half+1] + b1;
                if (MODE == 0) {
                    int b_ = row / SC;
                    int sdx = row - b_ * SC;
                    float* dst; size_t idx;
                    if (region == 0) {
                        dst = g_Q; idx = (((size_t)b_*HEADSC + h)*SC + sdx)*HDIMC + d0;
                    } else if (region == 1) {
                        dst = g_K; idx = (((size_t)b_*HEADSC + h)*TC + (sdx+1))*HDIMC + d0;
                    } else {
                        dst = g_V; idx = (((size_t)b_*HEADSC + h)*TC + (sdx+1))*HDIMC + d0;
                    }
                    *(float2*)(dst + idx) = make_float2(f2tff(x0), f2tff(x1));
                } else {
                    *(float2*)(C + (size_t)row*NW + gc) = make_float2(x0, x1);
                }
            }
        }
    }
}

// ---------------------------------------------------------------------------
// image token K/V (rounded stores)
// ---------------------------------------------------------------------------
__global__ __launch_bounds__(256) void k_img(const float* __restrict__ img,
                                             const float* __restrict__ ukw,
                                             const float* __restrict__ ukb,
                                             const float* __restrict__ uvw,
                                             const float* __restrict__ uvb)
{
    int gw   = (blockIdx.x * blockDim.x + threadIdx.x) >> 5;
    int lane = threadIdx.x & 31;
    int which = gw >> 12;
    int rem = gw & 4095;
    int b_ = rem >> 10;
    int j  = rem & 1023;
    const float* w  = which ? uvw : ukw;
    const float* bb = which ? uvb : ukb;

    const float4* x4 = (const float4*)(img + (size_t)b_*1024);
    const float4* w4 = (const float4*)(w + (size_t)j*1024);
    float s = 0.f;
    for (int e = lane; e < 256; e += 32) {
        float4 a = x4[e], b = w4[e];
        s += a.x*b.x + a.y*b.y + a.z*b.z + a.w*b.w;
    }
    #pragma unroll
    for (int o = 16; o; o >>= 1) s += __shfl_xor_sync(0xffffffffu, s, o);
    if (lane == 0) {
        int h = j >> 6, d = j & 63;
        float* dst = which ? g_V : g_K;
        dst[(((size_t)b_*HEADSC + h)*TC + 0)*HDIMC + d] = f2tff(s + bb[j]);
    }
}

// ---------------------------------------------------------------------------
// Attention: mma.sync tf32, cp.async tile loads (inputs pre-rounded).
// Qs [q][d] stride 68; Ks [t][d] stride 68; Vs [t][d] stride 72; Ps [q][k] 68.
// ---------------------------------------------------------------------------
#define SQA 68
#define SKT 68
#define SVT 72
#define SMEM_ATTN ((64*SQA + 64*SKT + 64*SVT + 64*SQA + 128 + 64) * 4)

__global__ __launch_bounds__(256) void k_attn(const float* __restrict__ amask)
{
    extern __shared__ __align__(16) float smf[];
    float* Qs = smf;                    // [q][d]
    float* Ks = Qs + 64*SQA;            // [t][d]
    float* Vs = Ks + 64*SKT;            // [t][d]
    unsigned* Ps = (unsigned*)(Vs + 64*SVT);   // [q][k] tf32
    float* red = (float*)(Ps + 64*SQA); // [2][64]
    float* msk = red + 128;             // [64]

    const int tid = threadIdx.x;
    const int qt = blockIdx.x, h = blockIdx.y, b_ = blockIdx.z;
    const int q0 = qt * 64;
    const float* Qg = g_Q + (((size_t)b_*HEADSC + h)*SC) * HDIMC;
    const float* Kg = g_K + (((size_t)b_*HEADSC + h)*TC) * HDIMC;
    const float* Vg = g_V + (((size_t)b_*HEADSC + h)*TC) * HDIMC;

    // Q tile via cp.async (zero-fill rows >= SC)
    #pragma unroll
    for (int i = 0; i < 4; i++) {
        int f = tid + i*256;
        int q = f >> 4, c = (f & 15) << 2;
        int gq = q0 + q;
        CP16(smem_u32(Qs + q*SQA + c), Qg + (size_t)gq*HDIMC + c,
             (gq < SC) ? 16 : 0);
    }
    CP_COMMIT();

    const int wid = tid >> 5, lane = tid & 31;
    const int wm = wid >> 1, wn = wid & 1;    // 4 x 2 warps
    const int rq = lane >> 2, cq = lane & 3;
    const int row0 = wm*16 + rq;

    float o[4][4] = {};
    float lsum[2] = {0.f, 0.f};
    const int nkt = min(qt + 2, 16);

    for (int kt = 0; kt < nkt; kt++) {
        const int k0 = kt * 64;
        __syncthreads();   // prev iter's reads of Ks/Vs/Ps done
        #pragma unroll
        for (int i = 0; i < 4; i++) {
            int f = tid + i*256;
            int kk = f >> 4, c = (f & 15) << 2;
            CP16(smem_u32(Ks + kk*SKT + c), Kg + (size_t)(k0+kk)*HDIMC + c, 16);
            CP16(smem_u32(Vs + kk*SVT + c), Vg + (size_t)(k0+kk)*HDIMC + c, 16);
        }
        CP_COMMIT();
        if (tid < 64) {
            int j = k0 + tid;
            msk[tid] = (j == 0) ? 0.f : amask[(size_t)b_*SC + j - 1];
        }
        CP_WAIT(0);
        __syncthreads();

        // S = Q K^T : A = Qs[q][d], B = Ks[t][d] (col-major as B[n][k])
        float s_[4][4] = {};
        #pragma unroll
        for (int kc = 0; kc < 64; kc += 8) {
            unsigned af[4];
            af[0] = __float_as_uint(Qs[(row0  )*SQA + kc + cq]);
            af[1] = __float_as_uint(Qs[(row0+8)*SQA + kc + cq]);
            af[2] = __float_as_uint(Qs[(row0  )*SQA + kc + cq + 4]);
            af[3] = __float_as_uint(Qs[(row0+8)*SQA + kc + cq + 4]);
            #pragma unroll
            for (int nt = 0; nt < 4; nt++) {
                int col = wn*32 + nt*8 + rq;
                unsigned bf[2] = {
                    __float_as_uint(Ks[col*SKT + kc + cq]),
                    __float_as_uint(Ks[col*SKT + kc + cq + 4]) };
                mma_tf32(s_[nt], af, bf);
            }
        }

        // exp + causal mask, P -> smem (tf32)
        const int gq0 = q0 + row0;
        #pragma unroll
        for (int nt = 0; nt < 4; nt++) {
            int lc = wn*32 + nt*8 + 2*cq;
            int gc = k0 + lc;
            float m0 = msk[lc], m1 = msk[lc+1];
            float p00 = (gc     <= gq0+1) ? __expf(s_[nt][0]*0.125f + m0) : 0.f;
            float p01 = (gc + 1 <= gq0+1) ? __expf(s_[nt][1]*0.125f + m1) : 0.f;
            float p10 = (gc     <= gq0+9) ? __expf(s_[nt][2]*0.125f + m0) : 0.f;
            float p11 = (gc + 1 <= gq0+9) ? __expf(s_[nt][3]*0.125f + m1) : 0.f;
            lsum[0] += p00 + p01;
            lsum[1] += p10 + p11;
            Ps[(row0  )*SQA + lc    ] = f2tf(p00);
            Ps[(row0  )*SQA + lc + 1] = f2tf(p01);
            Ps[(row0+8)*SQA + lc    ] = f2tf(p10);
            Ps[(row0+8)*SQA + lc + 1] = f2tf(p11);
        }
        __syncthreads();

        // O += P V : A = Ps[q][k], B = Vs[t][d] as B[k][n]
        #pragma unroll
        for (int kc = 0; kc < 64; kc += 8) {
            unsigned af[4];
            af[0] = Ps[(row0  )*SQA + kc + cq];
            af[1] = Ps[(row0+8)*SQA + kc + cq];
            af[2] = Ps[(row0  )*SQA + kc + cq + 4];
            af[3] = Ps[(row0+8)*SQA + kc + cq + 4];
            #pragma unroll
            for (int nt = 0; nt < 4; nt++) {
                int col = wn*32 + nt*8 + rq;
                unsigned bf[2] = {
                    __float_as_uint(Vs[(kc + cq    )*SVT + col]),
                    __float_as_uint(Vs[(kc + cq + 4)*SVT + col]) };
                mma_tf32(o[nt], af, bf);
            }
        }
    }

    #pragma unroll
    for (int i = 0; i < 2; i++) {
        lsum[i] += __shfl_xor_sync(0xffffffffu, lsum[i], 1);
        lsum[i] += __shfl_xor_sync(0xffffffffu, lsum[i], 2);
    }
    __syncthreads();
    if (cq == 0) {
        red[wn*64 + row0    ] = lsum[0];
        red[wn*64 + row0 + 8] = lsum[1];
    }
    __syncthreads();
    const float inv0 = 1.f / (red[row0    ] + red[64 + row0    ]);
    const float inv1 = 1.f / (red[row0 + 8] + red[64 + row0 + 8]);

    float* AOg = g_AO + (size_t)b_*SC*EMBEDC + h*HDIMC;
    const int s0 = q0 + row0;
    #pragma unroll
    for (int nt = 0; nt < 4; nt++) {
        int d = wn*32 + nt*8 + 2*cq;
        if (s0 < SC)
            *(float2*)(AOg + (size_t)s0*EMBEDC + d) =
                make_float2(f2tff(o[nt][0]*inv0), f2tff(o[nt][1]*inv0));
        if (s0 + 8 < SC)
            *(float2*)(AOg + (size_t)(s0+8)*EMBEDC + d) =
                make_float2(f2tff(o[nt][2]*inv1), f2tff(o[nt][3]*inv1));
    }
}

// ---------------------------------------------------------------------------
extern "C" void kernel_launch(void* const* d_in, const int* in_sizes, int n_in,
                              void* d_out, int out_size)
{
    (void)in_sizes; (void)n_in; (void)out_size;
    const float* word  = (const float*)d_in[0];
    const float* img   = (const float*)d_in[1];
    const float* amask = (const float*)d_in[2];
    const float* caw   = (const float*)d_in[3];
    const float* cab   = (const float*)d_in[4];
    const float* cpw   = (const float*)d_in[5];
    const float* cpb   = (const float*)d_in[6];
    const float* ukw   = (const float*)d_in[7];
    const float* ukb   = (const float*)d_in[8];
    const float* uvw   = (const float*)d_in[9];
    const float* uvb   = (const float*)d_in[10];
    float* out = (float*)d_out;

    void *p_Atf, *p_Wq, *p_Wp, *p_AO;
    cudaGetSymbolAddress(&p_Atf, g_Atf);
    cudaGetSymbolAddress(&p_Wq,  g_Wq);
    cudaGetSymbolAddress(&p_Wp,  g_Wp);
    cudaGetSymbolAddress(&p_AO,  g_AO);

    cudaFuncSetAttribute(k_gemm<3072,0>, cudaFuncAttributeMaxDynamicSharedMemorySize, SMEM_GEMM);
    cudaFuncSetAttribute(k_gemm<1024,1>, cudaFuncAttributeMaxDynamicSharedMemorySize, SMEM_GEMM);
    cudaFuncSetAttribute(k_attn, cudaFuncAttributeMaxDynamicSharedMemorySize, SMEM_ATTN);

    // prep: tf32 round-copies
    k_cvt<<<4092, 256>>>((const float4*)word, (float4*)p_Atf);
    k_cvt<<<3072, 256>>>((const float4*)caw,  (float4*)p_Wq);
    k_cvt<<<1024, 256>>>((const float4*)cpw,  (float4*)p_Wp);

    k_gemm<3072,0><<<dim3(24, 32), 256, SMEM_GEMM>>>(
        (const float*)p_Atf, (const float*)p_Wq, cab, nullptr);

    k_img<<<1024, 256>>>(img, ukw, ukb, uvw, uvb);

    dim3 ga(16, 16, 4);
    k_attn<<<ga, 256, SMEM_ATTN>>>(amask);

    k_gemm<1024,1><<<dim3(8, 32), 256, SMEM_GEMM>>>(
        (const float*)p_AO, (const float*)p_Wp, cpb, out);
}

// round 7
// speedup vs baseline: 2.8928x; 1.0014x over previous
#include <cuda_runtime.h>
#include <cstdint>

#define EMBEDC 1024
#define HEADSC 16
#define HDIMC  64
#define BC     4
#define SC     1023
#define TC     1024
#define M1     (BC*SC)   // 4092

// Scratch (allocation-free rule: __device__ globals)
__device__ float g_Q[BC*HEADSC*SC*HDIMC];    // [b][h][s][d], tf32-rounded
__device__ float g_K[BC*HEADSC*TC*HDIMC];    // [b][h][t][d], rounded
__device__ float g_V[BC*HEADSC*HDIMC*TC];    // [b][h][d][t]  TRANSPOSED, rounded
__device__ float g_AO[BC*SC*EMBEDC];         // attn out (B,S,E), rounded
__device__ float g_Atf[M1*EMBEDC];           // word, rounded
__device__ float g_WTq[3*EMBEDC*EMBEDC];     // c_attn_w^T  [n=3072][k=1024], rounded
__device__ float g_WTp[EMBEDC*EMBEDC];       // c_proj_w^T  [n=1024][k=1024], rounded

__device__ __forceinline__ unsigned f2tf(float x) {
    unsigned r; asm("cvt.rna.tf32.f32 %0, %1;" : "=r"(r) : "f"(x)); return r;
}
__device__ __forceinline__ float f2tff(float x) { return __uint_as_float(f2tf(x)); }

__device__ __forceinline__ void mma_tf32(float c[4], const unsigned a[4],
                                         const unsigned b[2]) {
    asm volatile(
        "mma.sync.aligned.m16n8k8.row.col.f32.tf32.tf32.f32 "
        "{%0,%1,%2,%3}, {%4,%5,%6,%7}, {%8,%9}, {%0,%1,%2,%3};"
        : "+f"(c[0]), "+f"(c[1]), "+f"(c[2]), "+f"(c[3])
        : "r"(a[0]), "r"(a[1]), "r"(a[2]), "r"(a[3]), "r"(b[0]), "r"(b[1]));
}

__device__ __forceinline__ uint32_t smem_u32(const void* p) {
    uint32_t a;
    asm("{ .reg .u64 t; cvta.to.shared.u64 t, %1; cvt.u32.u64 %0, t; }"
        : "=r"(a) : "l"(p));
    return a;
}
#define CP16(dst, src, sz) \
    asm volatile("cp.async.cg.shared.global [%0], [%1], 16, %2;" \
                 :: "r"(dst), "l"(src), "r"((uint32_t)(sz)) : "memory")
#define CP_COMMIT() asm volatile("cp.async.commit_group;" ::: "memory")
#define CP_WAIT(n)  asm volatile("cp.async.wait_group %0;" :: "n"(n) : "memory")
#define LDSM4(r0,r1,r2,r3, addr) \
    asm volatile("ldmatrix.sync.aligned.m8n8.x4.shared.b16 {%0,%1,%2,%3}, [%4];" \
                 : "=r"(r0),"=r"(r1),"=r"(r2),"=r"(r3) : "r"(addr))

// ---------------------------------------------------------------------------
// Prep: tf32 round-copy and transpose+round
// ---------------------------------------------------------------------------
__global__ __launch_bounds__(256) void k_cvt(const float4* __restrict__ in,
                                             float4* __restrict__ out)
{
    size_t i = (size_t)blockIdx.x * 256 + threadIdx.x;
    float4 v = in[i];
    out[i] = make_float4(f2tff(v.x), f2tff(v.y), f2tff(v.z), f2tff(v.w));
}

__global__ __launch_bounds__(256) void k_transp(const float* __restrict__ W,
                                                float* __restrict__ WT, int N)
{
    __shared__ float t[32][33];
    int bx = blockIdx.x * 32, by = blockIdx.y * 32;
    int tx = threadIdx.x & 31, ty = threadIdx.x >> 5;   // 32 x 8
    #pragma unroll
    for (int j = 0; j < 4; j++)
        t[ty + j*8][tx] = W[(size_t)(by + ty + j*8) * N + bx + tx];
    __syncthreads();
    #pragma unroll
    for (int j = 0; j < 4; j++)
        WT[(size_t)(bx + ty + j*8) * 1024 + by + tx] = f2tff(t[tx][ty + j*8]);
}

// ---------------------------------------------------------------------------
// tf32 GEMM: CTA 128x256, 8 warps (2x4), warp tile 64x64, ldmatrix A+B,
// 3-stage cp.async pipeline, ONE sync per K16 stage.
// A: [M1][1024] k-contig (rounded). Wt: [n][1024] k-contig (rounded).
// MODE 0: qkv scatter (Q/K rounded, V transposed); MODE 1: C = A*W + b.
// ---------------------------------------------------------------------------
#define NSTG 3
#define ATW 20
#define BTW 20
#define A_WORDS (128*ATW)      // 2560
#define B_WORDS (256*BTW)      // 5120
#define A_BYTES (A_WORDS*4)
#define STG_BYTES ((A_WORDS + B_WORDS)*4)   // 30720
#define SMEM_GEMM (NSTG*STG_BYTES)          // 92160

template<int MODE>
__global__ __launch_bounds__(256) void k_gemm(const float* __restrict__ A,
                                              const float* __restrict__ Wt,
                                              const float* __restrict__ bias,
                                              float* __restrict__ C)
{
    extern __shared__ float smf[];
    const uint32_t sb = smem_u32(smf);
    const int tid = threadIdx.x;
    const int bm = blockIdx.y * 128;
    const int bn = blockIdx.x * 256;
    const int wid = tid >> 5, lane = tid & 31;
    const int wm = wid >> 2, wn = wid & 3;     // 2 x 4 warps, 64x64 tiles
    const int rq = lane >> 2, cq = lane & 3;
    const int j = lane >> 3, r = lane & 7;

    const uint32_t a_lm = ((wm*64 + (j&1)*8 + r)*ATW + (j>>1)*4) * 4;
    const uint32_t b_lm = ((wn*64 + (j>>1)*8 + r)*BTW + (j&1)*4) * 4;

    float acc[4][8][4] = {};

    auto issue = [&](int kt, int s) {
        const int kof = kt * 16;
        uint32_t asp = sb + s*STG_BYTES;
        uint32_t bsp = asp + A_BYTES;
        #pragma unroll
        for (int i = 0; i < 2; i++) {
            int f = tid + i*256;
            int row = f >> 2, c = (f & 3) * 4;
            int gr = bm + row;
            CP16(asp + (row*ATW + c)*4, A + (size_t)gr*1024 + kof + c,
                 (gr < M1) ? 16 : 0);
        }
        #pragma unroll
        for (int i = 0; i < 4; i++) {
            int f = tid + i*256;
            int row = f >> 2, c = (f & 3) * 4;
            CP16(bsp + (row*BTW + c)*4,
                 Wt + (size_t)(bn + row)*1024 + kof + c, 16);
        }
        CP_COMMIT();
    };

    issue(0, 0);
    issue(1, 1);

    int s = 0;
    for (int kt = 0; kt < 64; kt++) {
        if (kt < 63) { CP_WAIT(1); } else { CP_WAIT(0); }
        __syncthreads();
        if (kt + 2 < 64) {
            int s2 = s + 2; if (s2 >= NSTG) s2 -= NSTG;
            issue(kt + 2, s2);
        }
        const uint32_t asp = sb + s*STG_BYTES;
        const uint32_t bsp = asp + A_BYTES;

        #pragma unroll
        for (int k0 = 0; k0 < 16; k0 += 8) {
            unsigned af[4][4], bf[8][2];
            #pragma unroll
            for (int mt = 0; mt < 4; mt++)
                LDSM4(af[mt][0], af[mt][1], af[mt][2], af[mt][3],
                      asp + a_lm + (mt*16*ATW + k0)*4);
            #pragma unroll
            for (int p = 0; p < 4; p++)
                LDSM4(bf[2*p][0], bf[2*p][1], bf[2*p+1][0], bf[2*p+1][1],
                      bsp + b_lm + (p*16*BTW + k0)*4);
            #pragma unroll
            for (int mt = 0; mt < 4; mt++)
                #pragma unroll
                for (int nt = 0; nt < 8; nt++)
                    mma_tf32(acc[mt][nt], af[mt], bf[nt]);
        }
        if (++s >= NSTG) s -= NSTG;
    }

    // ---- epilogue ----
    #pragma unroll
    for (int nt = 0; nt < 8; nt++) {
        const int gc = bn + wn*64 + nt*8 + 2*cq;
        const float b0 = bias[gc], b1 = bias[gc+1];
        int region = 0, h = 0, d0 = 0;
        if (MODE == 0) {
            region = gc >> 10;
            int w0 = gc & 1023;
            h = w0 >> 6; d0 = w0 & 63;
        }
        #pragma unroll
        for (int mt = 0; mt < 4; mt++) {
            #pragma unroll
            for (int half = 0; half < 2; half++) {
                int row = bm + wm*64 + mt*16 + rq + 8*half;
                if (row >= M1) continue;
                float x0 = acc[mt][nt][2*half]   + b0;
                float x1 = acc[mt][nt][2*half+1] + b1;
                if (MODE == 0) {
                    int b_ = row / SC;
                    int sdx = row - b_ * SC;
                    if (region == 0) {
                        size_t idx = (((size_t)b_*HEADSC + h)*SC + sdx)*HDIMC + d0;
                        *(float2*)(g_Q + idx) = make_float2(f2tff(x0), f2tff(x1));
                    } else if (region == 1) {
                        size_t idx = (((size_t)b_*HEADSC + h)*TC + (sdx+1))*HDIMC + d0;
                        *(float2*)(g_K + idx) = make_float2(f2tff(x0), f2tff(x1));
                    } else {
                        size_t idx = (((size_t)b_*HEADSC + h)*HDIMC + d0)*TC + (sdx+1);
                        g_V[idx]        = f2tff(x0);
                        g_V[idx + 1024] = f2tff(x1);
                    }
                } else {
                    *(float2*)(C + (size_t)row*1024 + gc) = make_float2(x0, x1);
                }
            }
        }
    }
}

// ---------------------------------------------------------------------------
// image token K/V (V transposed)
// ---------------------------------------------------------------------------
__global__ __launch_bounds__(256) void k_img(const float* __restrict__ img,
                                             const float* __restrict__ ukw,
                                             const float* __restrict__ ukb,
                                             const float* __restrict__ uvw,
                                             const float* __restrict__ uvb)
{
    int gw   = (blockIdx.x * blockDim.x + threadIdx.x) >> 5;
    int lane = threadIdx.x & 31;
    int which = gw >> 12;
    int rem = gw & 4095;
    int b_ = rem >> 10;
    int jj = rem & 1023;
    const float* w  = which ? uvw : ukw;
    const float* bb = which ? uvb : ukb;

    const float4* x4 = (const float4*)(img + (size_t)b_*1024);
    const float4* w4 = (const float4*)(w + (size_t)jj*1024);
    float s = 0.f;
    for (int e = lane; e < 256; e += 32) {
        float4 a = x4[e], b = w4[e];
        s += a.x*b.x + a.y*b.y + a.z*b.z + a.w*b.w;
    }
    #pragma unroll
    for (int o = 16; o; o >>= 1) s += __shfl_xor_sync(0xffffffffu, s, o);
    if (lane == 0) {
        int h = jj >> 6, d = jj & 63;
        float v = f2tff(s + bb[jj]);
        if (which)
            g_V[(((size_t)b_*HEADSC + h)*HDIMC + d)*TC + 0] = v;
        else
            g_K[(((size_t)b_*HEADSC + h)*TC + 0)*HDIMC + d] = v;
    }
}

// ---------------------------------------------------------------------------
// Attention: 128 threads (4 warps, 2x2), 64-query CTA tile, warp 32q x 32k.
// Q fragments register-resident; P kept in registers (shuffle permutation);
// K/V via cp.async double buffer; K & V fragments via ldmatrix; O cross-warp
// reduced once at the end.
// smem words: Qs 64*68 | K0 64*68 | V0 64*68 | K1 64*68 | V1 64*68 | msk 2*64 | red 128
// ---------------------------------------------------------------------------
#define ATT_Q   0
#define ATT_KV  (64*68)
#define ATT_MSK (ATT_KV + 4*64*68)
#define ATT_RED (ATT_MSK + 128)
#define SMEM_ATTN ((ATT_RED + 128) * 4)

__global__ __launch_bounds__(128) void k_attn(const float* __restrict__ amask)
{
    extern __shared__ float smf[];
    const uint32_t sb = smem_u32(smf);
    float* mskp = smf + ATT_MSK;
    float* red  = smf + ATT_RED;
    float* obuf = smf + ATT_KV;          // reused after mainloop

    const int tid = threadIdx.x;
    const int qt = blockIdx.x, h = blockIdx.y, b_ = blockIdx.z;
    const int q0 = qt * 64;
    const float* Qg = g_Q + (((size_t)b_*HEADSC + h)*SC) * HDIMC;
    const float* Kg = g_K + (((size_t)b_*HEADSC + h)*TC) * HDIMC;
    const float* Vg = g_V + (((size_t)b_*HEADSC + h)*HDIMC) * TC;  // [d][t]

    const int wid = tid >> 5, lane = tid & 31;
    const int wm = wid >> 1, wn = wid & 1;     // 2 x 2 warps
    const int rq = lane >> 2, cq = lane & 3;
    const int j = lane >> 3, r = lane & 7;

    // Q fill (group 0)
    #pragma unroll
    for (int i = 0; i < 8; i++) {
        int f = tid + i*128;
        int row = f >> 4, c = (f & 15) * 4;
        int gq = q0 + row;
        CP16(sb + ATT_Q*4 + (row*68 + c)*4, Qg + (size_t)gq*HDIMC + c,
             (gq < SC) ? 16 : 0);
    }
    CP_COMMIT();

    auto issueKV = [&](int kt, int bf) {
        int k0 = kt * 64;
        uint32_t kb = sb + (ATT_KV + bf*2*64*68)*4;
        uint32_t vb = kb + 64*68*4;
        #pragma unroll
        for (int i = 0; i < 8; i++) {
            int f = tid + i*128;
            int row = f >> 4, c = (f & 15) * 4;
            CP16(kb + (row*68 + c)*4, Kg + (size_t)(k0+row)*HDIMC + c, 16);
            CP16(vb + (row*68 + c)*4, Vg + (size_t)row*TC + k0 + c, 16);
        }
        if (tid < 64) {
            int kk = k0 + tid;
            mskp[bf*64 + tid] = (kk == 0) ? 0.f : amask[(size_t)b_*SC + kk - 1];
        }
        CP_COMMIT();
    };

    issueKV(0, 0);   // group 1

    unsigned qf[2][8][4];        // Q fragments, resident
    float o[2][8][4] = {};       // O accum (rows 2x16, d 64)
    float lsum[2][2] = {};       // [mt][row half]
    const int nkt = min(qt + 2, 16);

    for (int kt = 0; kt < nkt; kt++) {
        const int bf = kt & 1;
        __syncthreads();                       // all reads of buf bf^1 done
        if (kt + 1 < nkt) { issueKV(kt + 1, bf ^ 1); CP_WAIT(1); }
        else               { CP_WAIT(0); }
        __syncthreads();

        if (kt == 0) {
            #pragma unroll
            for (int mt = 0; mt < 2; mt++)
                #pragma unroll
                for (int dc = 0; dc < 8; dc++)
                    LDSM4(qf[mt][dc][0], qf[mt][dc][1], qf[mt][dc][2], qf[mt][dc][3],
                          sb + (ATT_Q + (wm*32 + mt*16 + (j&1)*8 + r)*68
                                + dc*8 + (j>>1)*4)*4);
        }

        const int k0 = kt * 64;
        if (k0 + wn*32 > q0 + wm*32 + 32) continue;    // fully-masked warp tile

        const uint32_t kb = sb + (ATT_KV + bf*2*64*68)*4;
        const uint32_t vb = kb + 64*68*4;

        // S = Q K^T (warp: 32q x 32k)
        float s_[2][4][4] = {};
        #pragma unroll
        for (int dc = 0; dc < 8; dc++) {
            unsigned kf[4][2];
            #pragma unroll
            for (int p = 0; p < 2; p++)
                LDSM4(kf[2*p][0], kf[2*p][1], kf[2*p+1][0], kf[2*p+1][1],
                      kb + ((wn*32 + (2*p + (j>>1))*8 + r)*68 + dc*8 + (j&1)*4)*4);
            #pragma unroll
            for (int mt = 0; mt < 2; mt++)
                #pragma unroll
                for (int nt = 0; nt < 4; nt++)
                    mma_tf32(s_[mt][nt], qf[mt][dc], kf[nt]);
        }

        // mask + exp -> P (tf32, in regs)
        unsigned pu[2][4][4];
        #pragma unroll
        for (int mt = 0; mt < 2; mt++) {
            const int gq0 = q0 + wm*32 + mt*16 + rq;
            #pragma unroll
            for (int nt = 0; nt < 4; nt++) {
                int lc = wn*32 + nt*8 + 2*cq;
                int gc = k0 + lc;
                float m0 = mskp[bf*64 + lc], m1 = mskp[bf*64 + lc + 1];
                float p00 = (gc     <= gq0+1) ? __expf(s_[mt][nt][0]*0.125f + m0) : 0.f;
                float p01 = (gc + 1 <= gq0+1) ? __expf(s_[mt][nt][1]*0.125f + m1) : 0.f;
                float p10 = (gc     <= gq0+9) ? __expf(s_[mt][nt][2]*0.125f + m0) : 0.f;
                float p11 = (gc + 1 <= gq0+9) ? __expf(s_[mt][nt][3]*0.125f + m1) : 0.f;
                lsum[mt][0] += p00 + p01;
                lsum[mt][1] += p10 + p11;
                pu[mt][nt][0] = f2tf(p00);
                pu[mt][nt][1] = f2tf(p01);
                pu[mt][nt][2] = f2tf(p10);
                pu[mt][nt][3] = f2tf(p11);
            }
        }

        // O += P V  (sum over this warp's 32 keys; V frags via ldmatrix of [d][t])
        const int L1 = (lane & ~3) | (cq >> 1);
        const int L2 = L1 + 2;
        const bool odd = (cq & 1);
        #pragma unroll
        for (int kc = 0; kc < 4; kc++) {
            unsigned vf[8][2];
            #pragma unroll
            for (int p = 0; p < 4; p++)
                LDSM4(vf[2*p][0], vf[2*p][1], vf[2*p+1][0], vf[2*p+1][1],
                      vb + (((2*p + (j>>1))*8 + r)*68 + wn*32 + kc*8 + (j&1)*4)*4);
            #pragma unroll
            for (int mt = 0; mt < 2; mt++) {
                unsigned s0 = __shfl_sync(0xffffffffu, pu[mt][kc][0], L1);
                unsigned s1 = __shfl_sync(0xffffffffu, pu[mt][kc][1], L1);
                unsigned s2 = __shfl_sync(0xffffffffu, pu[mt][kc][2], L1);
                unsigned s3 = __shfl_sync(0xffffffffu, pu[mt][kc][3], L1);
                unsigned t0 = __shfl_sync(0xffffffffu, pu[mt][kc][0], L2);
                unsigned t1 = __shfl_sync(0xffffffffu, pu[mt][kc][1], L2);
                unsigned t2 = __shfl_sync(0xffffffffu, pu[mt][kc][2], L2);
                unsigned t3 = __shfl_sync(0xffffffffu, pu[mt][kc][3], L2);
                unsigned af[4];
                af[0] = odd ? s1 : s0;
                af[1] = odd ? s3 : s2;
                af[2] = odd ? t1 : t0;
                af[3] = odd ? t3 : t2;
                #pragma unroll
                for (int nt = 0; nt < 8; nt++)
                    mma_tf32(o[mt][nt], af, vf[nt]);
            }
        }
    }

    // row sums: quad reduce, publish per wn
    #pragma unroll
    for (int mt = 0; mt < 2; mt++)
        #pragma unroll
        for (int i = 0; i < 2; i++) {
            lsum[mt][i] += __shfl_xor_sync(0xffffffffu, lsum[mt][i], 1);
            lsum[mt][i] += __shfl_xor_sync(0xffffffffu, lsum[mt][i], 2);
        }
    __syncthreads();                 // mainloop fully done; smem reusable
    if (cq == 0) {
        #pragma unroll
        for (int mt = 0; mt < 2; mt++) {
            int rr = wm*32 + mt*16 + rq;
            red[wn*64 + rr]     = lsum[mt][0];
            red[wn*64 + rr + 8] = lsum[mt][1];
        }
    }
    // wn==1 parks its O partial in smem
    if (wn == 1) {
        #pragma unroll
        for (int mt = 0; mt < 2; mt++)
            #pragma unroll
            for (int nt = 0; nt < 8; nt++) {
                int rr = wm*32 + mt*16 + rq;
                int d = nt*8 + 2*cq;
                obuf[(rr    )*68 + d]     = o[mt][nt][0];
                obuf[(rr    )*68 + d + 1] = o[mt][nt][1];
                obuf[(rr + 8)*68 + d]     = o[mt][nt][2];
                obuf[(rr + 8)*68 + d + 1] = o[mt][nt][3];
            }
    }
    __syncthreads();

    if (wn == 0) {
        float* AOg = g_AO + (size_t)b_*SC*EMBEDC + h*HDIMC;
        #pragma unroll
        for (int mt = 0; mt < 2; mt++) {
            int rr = wm*32 + mt*16 + rq;
            float inv0 = 1.f / (red[rr]     + red[64 + rr]);
            float inv1 = 1.f / (red[rr + 8] + red[64 + rr + 8]);
            int s0 = q0 + rr;
            #pragma unroll
            for (int nt = 0; nt < 8; nt++) {
                int d = nt*8 + 2*cq;
                if (s0 < SC) {
                    float y0 = (o[mt][nt][0] + obuf[rr*68 + d])     * inv0;
                    float y1 = (o[mt][nt][1] + obuf[rr*68 + d + 1]) * inv0;
                    *(float2*)(AOg + (size_t)s0*EMBEDC + d) =
                        make_float2(f2tff(y0), f2tff(y1));
                }
                if (s0 + 8 < SC) {
                    float y2 = (o[mt][nt][2] + obuf[(rr+8)*68 + d])     * inv1;
                    float y3 = (o[mt][nt][3] + obuf[(rr+8)*68 + d + 1]) * inv1;
                    *(float2*)(AOg + (size_t)(s0+8)*EMBEDC + d) =
                        make_float2(f2tff(y2), f2tff(y3));
                }
            }
        }
    }
}

// ---------------------------------------------------------------------------
extern "C" void kernel_launch(void* const* d_in, const int* in_sizes, int n_in,
                              void* d_out, int out_size)
{
    (void)in_sizes; (void)n_in; (void)out_size;
    const float* word  = (const float*)d_in[0];
    const float* img   = (const float*)d_in[1];
    const float* amask = (const float*)d_in[2];
    const float* caw   = (const float*)d_in[3];
    const float* cab   = (const float*)d_in[4];
    const float* cpw   = (const float*)d_in[5];
    const float* cpb   = (const float*)d_in[6];
    const float* ukw   = (const float*)d_in[7];
    const float* ukb   = (const float*)d_in[8];
    const float* uvw   = (const float*)d_in[9];
    const float* uvb   = (const float*)d_in[10];
    float* out = (float*)d_out;

    void *p_Atf, *p_WTq, *p_WTp, *p_AO;
    cudaGetSymbolAddress(&p_Atf, g_Atf);
    cudaGetSymbolAddress(&p_WTq, g_WTq);
    cudaGetSymbolAddress(&p_WTp, g_WTp);
    cudaGetSymbolAddress(&p_AO,  g_AO);

    cudaFuncSetAttribute(k_gemm<0>, cudaFuncAttributeMaxDynamicSharedMemorySize, SMEM_GEMM);
    cudaFuncSetAttribute(k_gemm<1>, cudaFuncAttributeMaxDynamicSharedMemorySize, SMEM_GEMM);
    cudaFuncSetAttribute(k_attn, cudaFuncAttributeMaxDynamicSharedMemorySize, SMEM_ATTN);

    // prep: round A; transpose+round weights
    k_cvt<<<4092, 256>>>((const float4*)word, (float4*)p_Atf);
    k_transp<<<dim3(96, 32), 256>>>(caw, (float*)p_WTq, 3072);
    k_transp<<<dim3(32, 32), 256>>>(cpw, (float*)p_WTp, 1024);

    k_gemm<0><<<dim3(12, 32), 256, SMEM_GEMM>>>(
        (const float*)p_Atf, (const float*)p_WTq, cab, nullptr);

    k_img<<<1024, 256>>>(img, ukw, ukb, uvw, uvb);

    dim3 ga(16, 16, 4);
    k_attn<<<ga, 128, SMEM_ATTN>>>(amask);

    k_gemm<1><<<dim3(4, 32), 256, SMEM_GEMM>>>(
        (const float*)p_AO, (const float*)p_WTp, cpb, out);
}

// round 8
// speedup vs baseline: 5.2764x; 1.8240x over previous
#include <cuda_runtime.h>
#include <cuda_fp16.h>
#include <cstdint>

#define EMBEDC 1024
#define HEADSC 16
#define HDIMC  64
#define BC     4
#define SC     1023
#define TC     1024
#define M1     (BC*SC)   // 4092

// Scratch (allocation-free rule: __device__ globals), all fp16
__device__ __align__(16) __half g_Qh[BC*HEADSC*SC*HDIMC];    // [b][h][s][d]
__device__ __align__(16) __half g_Kh[BC*HEADSC*TC*HDIMC];    // [b][h][t][d]
__device__ __align__(16) __half g_Vh[BC*HEADSC*HDIMC*TC];    // [b][h][d][t] transposed
__device__ __align__(16) __half g_AOh[BC*SC*EMBEDC];         // attn out (B,S,E)
__device__ __align__(16) __half g_Ah[M1*EMBEDC];             // word
__device__ __align__(16) __half g_WTqh[3*EMBEDC*EMBEDC];     // c_attn_w^T [n][k]
__device__ __align__(16) __half g_WTph[EMBEDC*EMBEDC];       // c_proj_w^T [n][k]

__device__ __forceinline__ unsigned packh2(float a, float b) {
    __half2 h = __floats2half2_rn(a, b);
    return *(unsigned*)&h;
}

__device__ __forceinline__ void mma_f16(float c[4], const unsigned a[4],
                                        const unsigned b[2]) {
    asm volatile(
        "mma.sync.aligned.m16n8k16.row.col.f32.f16.f16.f32 "
        "{%0,%1,%2,%3}, {%4,%5,%6,%7}, {%8,%9}, {%0,%1,%2,%3};"
        : "+f"(c[0]), "+f"(c[1]), "+f"(c[2]), "+f"(c[3])
        : "r"(a[0]), "r"(a[1]), "r"(a[2]), "r"(a[3]), "r"(b[0]), "r"(b[1]));
}

__device__ __forceinline__ uint32_t smem_u32(const void* p) {
    uint32_t a;
    asm("{ .reg .u64 t; cvta.to.shared.u64 t, %1; cvt.u32.u64 %0, t; }"
        : "=r"(a) : "l"(p));
    return a;
}
#define CP16(dst, src, sz) \
    asm volatile("cp.async.cg.shared.global [%0], [%1], 16, %2;" \
                 :: "r"(dst), "l"(src), "r"((uint32_t)(sz)) : "memory")
#define CP_COMMIT() asm volatile("cp.async.commit_group;" ::: "memory")
#define CP_WAIT(n)  asm volatile("cp.async.wait_group %0;" :: "n"(n) : "memory")
#define LDSM4(r0,r1,r2,r3, addr) \
    asm volatile("ldmatrix.sync.aligned.m8n8.x4.shared.b16 {%0,%1,%2,%3}, [%4];" \
                 : "=r"(r0),"=r"(r1),"=r"(r2),"=r"(r3) : "r"(addr))

// ---------------------------------------------------------------------------
// Prep: fp16 round-copy and transpose+round
// ---------------------------------------------------------------------------
__global__ __launch_bounds__(256) void k_cvtH(const float4* __restrict__ in,
                                              uint2* __restrict__ out)
{
    size_t i = (size_t)blockIdx.x * 256 + threadIdx.x;
    float4 v = in[i];
    out[i] = make_uint2(packh2(v.x, v.y), packh2(v.z, v.w));
}

__global__ __launch_bounds__(256) void k_transpH(const float* __restrict__ W,
                                                 __half* __restrict__ WT, int N)
{
    __shared__ float t[32][33];
    int bx = blockIdx.x * 32, by = blockIdx.y * 32;
    int tx = threadIdx.x & 31, ty = threadIdx.x >> 5;   // 32 x 8
    #pragma unroll
    for (int jj = 0; jj < 4; jj++)
        t[ty + jj*8][tx] = W[(size_t)(by + ty + jj*8) * N + bx + tx];
    __syncthreads();
    #pragma unroll
    for (int jj = 0; jj < 4; jj++)
        WT[(size_t)(bx + ty + jj*8) * 1024 + by + tx] =
            __float2half_rn(t[tx][ty + jj*8]);
}

// ---------------------------------------------------------------------------
// fp16 GEMM: CTA 128x128, 8 warps (2x4) of 64x32, K32 stages, 3-stage
// cp.async pipeline, 1 sync/stage, ldmatrix A+B, fp32 accum.
// A: half [M1][1024]; Wt: half [n][1024]. MODE 0: qkv scatter; 1: C=A*W+b.
// ---------------------------------------------------------------------------
#define NSTG 3
#define KS   32
#define TSH  40              // smem row stride, halves (80B: ldmatrix conflict-free)
#define T_HALVES (128*TSH)   // per operand per stage
#define STG_BYTES (2*T_HALVES*2)       // 20480
#define SMEM_GEMM (NSTG*STG_BYTES)     // 61440

template<int MODE>
__global__ __launch_bounds__(256) void k_gemm(const __half* __restrict__ A,
                                              const __half* __restrict__ Wt,
                                              const float* __restrict__ bias,
                                              float* __restrict__ C)
{
    extern __shared__ char smc[];
    const uint32_t sb = smem_u32(smc);
    const int tid = threadIdx.x;
    const int bm = blockIdx.y * 128;
    const int bn = blockIdx.x * 128;
    const int wid = tid >> 5, lane = tid & 31;
    const int wm = wid >> 2, wn = wid & 3;     // 2 x 4 warps, 64x32 tiles
    const int rq = lane >> 2, cq = lane & 3;
    const int j = lane >> 3, r = lane & 7;

    const uint32_t a_lm = ((wm*64 + (j&1)*8 + r)*TSH + (j>>1)*8) * 2;
    const uint32_t b_lm = ((wn*32 + (j>>1)*8 + r)*TSH + (j&1)*8) * 2;

    float acc[4][4][4] = {};

    auto issue = [&](int kt, int s) {
        const int kof = kt * KS;
        uint32_t asp = sb + s*STG_BYTES;
        uint32_t bsp = asp + T_HALVES*2;
        #pragma unroll
        for (int i = 0; i < 2; i++) {
            int f = tid + i*256;
            int row = f >> 2, c = (f & 3) * 8;
            int gr = bm + row;
            CP16(asp + (row*TSH + c)*2, A + (size_t)gr*1024 + kof + c,
                 (gr < M1) ? 16 : 0);
        }
        #pragma unroll
        for (int i = 0; i < 2; i++) {
            int f = tid + i*256;
            int row = f >> 2, c = (f & 3) * 8;
            CP16(bsp + (row*TSH + c)*2, Wt + (size_t)(bn + row)*1024 + kof + c, 16);
        }
        CP_COMMIT();
    };

    issue(0, 0);
    issue(1, 1);

    int s = 0;
    for (int kt = 0; kt < 32; kt++) {
        if (kt < 31) { CP_WAIT(1); } else { CP_WAIT(0); }
        __syncthreads();
        if (kt + 2 < 32) {
            int s2 = s + 2; if (s2 >= NSTG) s2 -= NSTG;
            issue(kt + 2, s2);
        }
        const uint32_t asp = sb + s*STG_BYTES;
        const uint32_t bsp = asp + T_HALVES*2;

        #pragma unroll
        for (int k0 = 0; k0 < 32; k0 += 16) {
            unsigned af[4][4], bf[4][2];
            #pragma unroll
            for (int mt = 0; mt < 4; mt++)
                LDSM4(af[mt][0], af[mt][1], af[mt][2], af[mt][3],
                      asp + a_lm + (mt*16*TSH + k0)*2);
            #pragma unroll
            for (int p = 0; p < 2; p++)
                LDSM4(bf[2*p][0], bf[2*p][1], bf[2*p+1][0], bf[2*p+1][1],
                      bsp + b_lm + (p*16*TSH + k0)*2);
            #pragma unroll
            for (int mt = 0; mt < 4; mt++)
                #pragma unroll
                for (int nt = 0; nt < 4; nt++)
                    mma_f16(acc[mt][nt], af[mt], bf[nt]);
        }
        if (++s >= NSTG) s -= NSTG;
    }

    // ---- epilogue ----
    #pragma unroll
    for (int nt = 0; nt < 4; nt++) {
        const int gc = bn + wn*32 + nt*8 + 2*cq;
        const float b0 = bias[gc], b1 = bias[gc+1];
        int region = 0, h = 0, d0 = 0;
        if (MODE == 0) {
            region = gc >> 10;
            int w0 = gc & 1023;
            h = w0 >> 6; d0 = w0 & 63;
        }
        #pragma unroll
        for (int mt = 0; mt < 4; mt++) {
            #pragma unroll
            for (int half = 0; half < 2; half++) {
                int row = bm + wm*64 + mt*16 + rq + 8*half;
                if (row >= M1) continue;
                float x0 = acc[mt][nt][2*half]   + b0;
                float x1 = acc[mt][nt][2*half+1] + b1;
                if (MODE == 0) {
                    int b_ = row / SC;
                    int sdx = row - b_ * SC;
                    if (region == 0) {
                        size_t idx = (((size_t)b_*HEADSC + h)*SC + sdx)*HDIMC + d0;
                        *(unsigned*)(g_Qh + idx) = packh2(x0, x1);
                    } else if (region == 1) {
                        size_t idx = (((size_t)b_*HEADSC + h)*TC + (sdx+1))*HDIMC + d0;
                        *(unsigned*)(g_Kh + idx) = packh2(x0, x1);
                    } else {
                        size_t idx = (((size_t)b_*HEADSC + h)*HDIMC + d0)*TC + (sdx+1);
                        g_Vh[idx]        = __float2half_rn(x0);
                        g_Vh[idx + 1024] = __float2half_rn(x1);
                    }
                } else {
                    *(float2*)(C + (size_t)row*1024 + gc) = make_float2(x0, x1);
                }
            }
        }
    }
}

// ---------------------------------------------------------------------------
// image token K/V (fp32 compute, fp16 store; V transposed)
// ---------------------------------------------------------------------------
__global__ __launch_bounds__(256) void k_img(const float* __restrict__ img,
                                             const float* __restrict__ ukw,
                                             const float* __restrict__ ukb,
                                             const float* __restrict__ uvw,
                                             const float* __restrict__ uvb)
{
    int gw   = (blockIdx.x * blockDim.x + threadIdx.x) >> 5;
    int lane = threadIdx.x & 31;
    int which = gw >> 12;
    int rem = gw & 4095;
    int b_ = rem >> 10;
    int jj = rem & 1023;
    const float* w  = which ? uvw : ukw;
    const float* bb = which ? uvb : ukb;

    const float4* x4 = (const float4*)(img + (size_t)b_*1024);
    const float4* w4 = (const float4*)(w + (size_t)jj*1024);
    float s = 0.f;
    for (int e = lane; e < 256; e += 32) {
        float4 a = x4[e], b = w4[e];
        s += a.x*b.x + a.y*b.y + a.z*b.z + a.w*b.w;
    }
    #pragma unroll
    for (int o = 16; o; o >>= 1) s += __shfl_xor_sync(0xffffffffu, s, o);
    if (lane == 0) {
        int h = jj >> 6, d = jj & 63;
        __half v = __float2half_rn(s + bb[jj]);
        if (which)
            g_Vh[(((size_t)b_*HEADSC + h)*HDIMC + d)*TC + 0] = v;
        else
            g_Kh[(((size_t)b_*HEADSC + h)*TC + 0)*HDIMC + d] = v;
    }
}

// ---------------------------------------------------------------------------
// Attention fp16: 128 threads (2x2 warps), 64-query tile, warp 32q x 32k.
// Q frags resident; P stays in registers (acc layout == fp16 A-frag layout);
// K/V double-buffered cp.async; O cross-warp reduced once at end.
// Byte layout: Q 9216 | KV bufs 4*9216 | msk 512 | red 512
// ---------------------------------------------------------------------------
#define AQ_B   0
#define AKV_B  9216
#define AMSK_B (AKV_B + 4*9216)
#define ARED_B (AMSK_B + 512)
#define SMEM_ATTN (ARED_B + 512)
#define QSTR 72              // smem row stride, halves (144B: conflict-free)

__global__ __launch_bounds__(128) void k_attn(const float* __restrict__ amask)
{
    extern __shared__ char smc[];
    const uint32_t sb = smem_u32(smc);
    float* mskp = (float*)(smc + AMSK_B);
    float* red  = (float*)(smc + ARED_B);
    float* obuf = (float*)(smc + AKV_B);   // reused after mainloop (16KB<36KB)

    const int tid = threadIdx.x;
    const int qt = blockIdx.x, h = blockIdx.y, b_ = blockIdx.z;
    const int q0 = qt * 64;
    const __half* Qg = g_Qh + (((size_t)b_*HEADSC + h)*SC) * HDIMC;
    const __half* Kg = g_Kh + (((size_t)b_*HEADSC + h)*TC) * HDIMC;
    const __half* Vg = g_Vh + (((size_t)b_*HEADSC + h)*HDIMC) * TC;  // [d][t]

    const int wid = tid >> 5, lane = tid & 31;
    const int wm = wid >> 1, wn = wid & 1;     // 2 x 2 warps
    const int rq = lane >> 2, cq = lane & 3;
    const int j = lane >> 3, r = lane & 7;

    // Q fill: 64 rows x 64 halves (8 CP16/row)
    #pragma unroll
    for (int i = 0; i < 4; i++) {
        int f = tid + i*128;
        int row = f >> 3, c = (f & 7) * 8;
        int gq = q0 + row;
        CP16(sb + AQ_B + (row*QSTR + c)*2, Qg + (size_t)gq*HDIMC + c,
             (gq < SC) ? 16 : 0);
    }
    CP_COMMIT();

    auto issueKV = [&](int kt, int bf) {
        int k0 = kt * 64;
        uint32_t kb = sb + AKV_B + bf*2*9216;
        uint32_t vb = kb + 9216;
        #pragma unroll
        for (int i = 0; i < 4; i++) {
            int f = tid + i*128;
            int row = f >> 3, c = (f & 7) * 8;
            CP16(kb + (row*QSTR + c)*2, Kg + (size_t)(k0+row)*HDIMC + c, 16);
            CP16(vb + (row*QSTR + c)*2, Vg + (size_t)row*TC + k0 + c, 16);
        }
        if (tid < 64) {
            int kk = k0 + tid;
            mskp[bf*64 + tid] = (kk == 0) ? 0.f : amask[(size_t)b_*SC + kk - 1];
        }
        CP_COMMIT();
    };

    issueKV(0, 0);

    unsigned qf[2][4][4];        // Q fragments (d in 4 k16 chunks)
    float o[2][8][4] = {};       // O accum
    float lsum[2][2] = {};
    const int nkt = min(qt + 2, 16);

    for (int kt = 0; kt < nkt; kt++) {
        const int bf = kt & 1;
        __syncthreads();
        if (kt + 1 < nkt) { issueKV(kt + 1, bf ^ 1); CP_WAIT(1); }
        else              { CP_WAIT(0); }
        __syncthreads();

        if (kt == 0) {
            #pragma unroll
            for (int mt = 0; mt < 2; mt++)
                #pragma unroll
                for (int dc = 0; dc < 4; dc++)
                    LDSM4(qf[mt][dc][0], qf[mt][dc][1], qf[mt][dc][2], qf[mt][dc][3],
                          sb + AQ_B + ((wm*32 + mt*16 + (j&1)*8 + r)*QSTR
                                       + dc*16 + (j>>1)*8)*2);
        }

        const int k0 = kt * 64;
        if (k0 + wn*32 > q0 + wm*32 + 32) continue;   // fully masked warp tile

        const uint32_t kb = sb + AKV_B + bf*2*9216;
        const uint32_t vb = kb + 9216;

        // S = Q K^T
        float s_[2][4][4] = {};
        #pragma unroll
        for (int dc = 0; dc < 4; dc++) {
            unsigned kf[4][2];
            #pragma unroll
            for (int p = 0; p < 2; p++)
                LDSM4(kf[2*p][0], kf[2*p][1], kf[2*p+1][0], kf[2*p+1][1],
                      kb + ((wn*32 + p*16 + (j>>1)*8 + r)*QSTR
                            + dc*16 + (j&1)*8)*2);
            #pragma unroll
            for (int mt = 0; mt < 2; mt++)
                #pragma unroll
                for (int nt = 0; nt < 4; nt++)
                    mma_f16(s_[mt][nt], qf[mt][dc], kf[nt]);
        }

        // mask + exp -> P packed half2 (acc layout == A-frag layout)
        unsigned pl[2][4][2];
        #pragma unroll
        for (int mt = 0; mt < 2; mt++) {
            const int gq0 = q0 + wm*32 + mt*16 + rq;
            #pragma unroll
            for (int nt = 0; nt < 4; nt++) {
                int lc = wn*32 + nt*8 + 2*cq;
                int gc = k0 + lc;
                float m0 = mskp[bf*64 + lc], m1 = mskp[bf*64 + lc + 1];
                float p00 = (gc     <= gq0+1) ? __expf(s_[mt][nt][0]*0.125f + m0) : 0.f;
                float p01 = (gc + 1 <= gq0+1) ? __expf(s_[mt][nt][1]*0.125f + m1) : 0.f;
                float p10 = (gc     <= gq0+9) ? __expf(s_[mt][nt][2]*0.125f + m0) : 0.f;
                float p11 = (gc + 1 <= gq0+9) ? __expf(s_[mt][nt][3]*0.125f + m1) : 0.f;
                lsum[mt][0] += p00 + p01;
                lsum[mt][1] += p10 + p11;
                pl[mt][nt][0] = packh2(p00, p01);
                pl[mt][nt][1] = packh2(p10, p11);
            }
        }

        // O += P V  (2 k16 chunks over this warp's 32 keys)
        #pragma unroll
        for (int kc = 0; kc < 2; kc++) {
            unsigned vf[8][2];
            #pragma unroll
            for (int p = 0; p < 4; p++)
                LDSM4(vf[2*p][0], vf[2*p][1], vf[2*p+1][0], vf[2*p+1][1],
                      vb + ((p*16 + (j>>1)*8 + r)*QSTR
                            + wn*32 + kc*16 + (j&1)*8)*2);
            #pragma unroll
            for (int mt = 0; mt < 2; mt++) {
                unsigned af[4];
                af[0] = pl[mt][2*kc][0];
                af[1] = pl[mt][2*kc][1];
                af[2] = pl[mt][2*kc+1][0];
                af[3] = pl[mt][2*kc+1][1];
                #pragma unroll
                for (int nt = 0; nt < 8; nt++)
                    mma_f16(o[mt][nt], af, vf[nt]);
            }
        }
    }

    // row sums: quad reduce, publish per wn
    #pragma unroll
    for (int mt = 0; mt < 2; mt++)
        #pragma unroll
        for (int i = 0; i < 2; i++) {
            lsum[mt][i] += __shfl_xor_sync(0xffffffffu, lsum[mt][i], 1);
            lsum[mt][i] += __shfl_xor_sync(0xffffffffu, lsum[mt][i], 2);
        }
    __syncthreads();
    if (cq == 0) {
        #pragma unroll
        for (int mt = 0; mt < 2; mt++) {
            int rr = wm*32 + mt*16 + rq;
            red[wn*64 + rr]     = lsum[mt][0];
            red[wn*64 + rr + 8] = lsum[mt][1];
        }
    }
    if (wn == 1) {
        #pragma unroll
        for (int mt = 0; mt < 2; mt++)
            #pragma unroll
            for (int nt = 0; nt < 8; nt++) {
                int rr = wm*32 + mt*16 + rq;
                int d = nt*8 + 2*cq;
                obuf[(rr    )*68 + d]     = o[mt][nt][0];
                obuf[(rr    )*68 + d + 1] = o[mt][nt][1];
                obuf[(rr + 8)*68 + d]     = o[mt][nt][2];
                obuf[(rr + 8)*68 + d + 1] = o[mt][nt][3];
            }
    }
    __syncthreads();

    if (wn == 0) {
        __half* AOg = g_AOh + (size_t)b_*SC*EMBEDC + h*HDIMC;
        #pragma unroll
        for (int mt = 0; mt < 2; mt++) {
            int rr = wm*32 + mt*16 + rq;
            float inv0 = 1.f / (red[rr]     + red[64 + rr]);
            float inv1 = 1.f / (red[rr + 8] + red[64 + rr + 8]);
            int s0 = q0 + rr;
            #pragma unroll
            for (int nt = 0; nt < 8; nt++) {
                int d = nt*8 + 2*cq;
                if (s0 < SC) {
                    float y0 = (o[mt][nt][0] + obuf[rr*68 + d])     * inv0;
                    float y1 = (o[mt][nt][1] + obuf[rr*68 + d + 1]) * inv0;
                    *(unsigned*)(AOg + (size_t)s0*EMBEDC + d) = packh2(y0, y1);
                }
                if (s0 + 8 < SC) {
                    float y2 = (o[mt][nt][2] + obuf[(rr+8)*68 + d])     * inv1;
                    float y3 = (o[mt][nt][3] + obuf[(rr+8)*68 + d + 1]) * inv1;
                    *(unsigned*)(AOg + (size_t)(s0+8)*EMBEDC + d) = packh2(y2, y3);
                }
            }
        }
    }
}

// ---------------------------------------------------------------------------
extern "C" void kernel_launch(void* const* d_in, const int* in_sizes, int n_in,
                              void* d_out, int out_size)
{
    (void)in_sizes; (void)n_in; (void)out_size;
    const float* word  = (const float*)d_in[0];
    const float* img   = (const float*)d_in[1];
    const float* amask = (const float*)d_in[2];
    const float* caw   = (const float*)d_in[3];
    const float* cab   = (const float*)d_in[4];
    const float* cpw   = (const float*)d_in[5];
    const float* cpb   = (const float*)d_in[6];
    const float* ukw   = (const float*)d_in[7];
    const float* ukb   = (const float*)d_in[8];
    const float* uvw   = (const float*)d_in[9];
    const float* uvb   = (const float*)d_in[10];
    float* out = (float*)d_out;

    void *p_Ah, *p_WTq, *p_WTp, *p_AO;
    cudaGetSymbolAddress(&p_Ah,  g_Ah);
    cudaGetSymbolAddress(&p_WTq, g_WTqh);
    cudaGetSymbolAddress(&p_WTp, g_WTph);
    cudaGetSymbolAddress(&p_AO,  g_AOh);

    cudaFuncSetAttribute(k_gemm<0>, cudaFuncAttributeMaxDynamicSharedMemorySize, SMEM_GEMM);
    cudaFuncSetAttribute(k_gemm<1>, cudaFuncAttributeMaxDynamicSharedMemorySize, SMEM_GEMM);
    cudaFuncSetAttribute(k_attn, cudaFuncAttributeMaxDynamicSharedMemorySize, SMEM_ATTN);

    // prep: round word; transpose+round weights
    k_cvtH<<<4092, 256>>>((const float4*)word, (uint2*)p_Ah);
    k_transpH<<<dim3(96, 32), 256>>>(caw, (__half*)p_WTq, 3072);
    k_transpH<<<dim3(32, 32), 256>>>(cpw, (__half*)p_WTp, 1024);

    k_gemm<0><<<dim3(24, 32), 256, SMEM_GEMM>>>(
        (const __half*)p_Ah, (const __half*)p_WTq, cab, nullptr);

    k_img<<<1024, 256>>>(img, ukw, ukb, uvw, uvb);

    dim3 ga(16, 16, 4);
    k_attn<<<ga, 128, SMEM_ATTN>>>(amask);

    k_gemm<1><<<dim3(8, 32), 256, SMEM_GEMM>>>(
        (const __half*)p_AO, (const __half*)p_WTp, cpb, out);
}

// round 13
// speedup vs baseline: 5.4722x; 1.0371x over previous
#include <cuda_runtime.h>
#include <cuda_fp16.h>
#include <cstdint>

#define EMBEDC 1024
#define HEADSC 16
#define HDIMC  64
#define BC     4
#define SC     1023
#define TC     1024
#define M1     (BC*SC)   // 4092

// Scratch (allocation-free rule: __device__ globals), all fp16
__device__ __align__(16) __half g_Qh[BC*HEADSC*SC*HDIMC];    // [b][h][s][d]
__device__ __align__(16) __half g_Kh[BC*HEADSC*TC*HDIMC];    // [b][h][t][d]
__device__ __align__(16) __half g_Vh[BC*HEADSC*HDIMC*TC];    // [b][h][d][t] transposed
__device__ __align__(16) __half g_AOh[BC*SC*EMBEDC];         // attn out (B,S,E)
__device__ __align__(16) __half g_Ah[M1*EMBEDC];             // word
__device__ __align__(16) __half g_WTqh[3*EMBEDC*EMBEDC];     // c_attn_w^T [n][k]
__device__ __align__(16) __half g_WTph[EMBEDC*EMBEDC];       // c_proj_w^T [n][k]

__device__ __forceinline__ unsigned packh2(float a, float b) {
    __half2 h = __floats2half2_rn(a, b);
    return *(unsigned*)&h;
}

__device__ __forceinline__ void mma_f16(float c[4], const unsigned a[4],
                                        const unsigned b[2]) {
    asm volatile(
        "mma.sync.aligned.m16n8k16.row.col.f32.f16.f16.f32 "
        "{%0,%1,%2,%3}, {%4,%5,%6,%7}, {%8,%9}, {%0,%1,%2,%3};"
        : "+f"(c[0]), "+f"(c[1]), "+f"(c[2]), "+f"(c[3])
        : "r"(a[0]), "r"(a[1]), "r"(a[2]), "r"(a[3]), "r"(b[0]), "r"(b[1]));
}

__device__ __forceinline__ uint32_t smem_u32(const void* p) {
    uint32_t a;
    asm("{ .reg .u64 t; cvta.to.shared.u64 t, %1; cvt.u32.u64 %0, t; }"
        : "=r"(a) : "l"(p));
    return a;
}
#define CP16(dst, src, sz) \
    asm volatile("cp.async.cg.shared.global [%0], [%1], 16, %2;" \
                 :: "r"(dst), "l"(src), "r"((uint32_t)(sz)) : "memory")
#define CP_COMMIT() asm volatile("cp.async.commit_group;" ::: "memory")
#define CP_WAIT(n)  asm volatile("cp.async.wait_group %0;" :: "n"(n) : "memory")
#define LDSM4(r0,r1,r2,r3, addr) \
    asm volatile("ldmatrix.sync.aligned.m8n8.x4.shared.b16 {%0,%1,%2,%3}, [%4];" \
                 : "=r"(r0),"=r"(r1),"=r"(r2),"=r"(r3) : "r"(addr))

// ---------------------------------------------------------------------------
// Prep: fp16 round-copy and transpose+round
// ---------------------------------------------------------------------------
__global__ __launch_bounds__(256) void k_cvtH(const float4* __restrict__ in,
                                              uint2* __restrict__ out)
{
    size_t i = (size_t)blockIdx.x * 256 + threadIdx.x;
    float4 v = in[i];
    out[i] = make_uint2(packh2(v.x, v.y), packh2(v.z, v.w));
}

__global__ __launch_bounds__(256) void k_transpH(const float* __restrict__ W,
                                                 __half* __restrict__ WT, int N)
{
    __shared__ float t[32][33];
    int bx = blockIdx.x * 32, by = blockIdx.y * 32;
    int tx = threadIdx.x & 31, ty = threadIdx.x >> 5;   // 32 x 8
    #pragma unroll
    for (int jj = 0; jj < 4; jj++)
        t[ty + jj*8][tx] = W[(size_t)(by + ty + jj*8) * N + bx + tx];
    __syncthreads();
    #pragma unroll
    for (int jj = 0; jj < 4; jj++)
        WT[(size_t)(bx + ty + jj*8) * 1024 + by + tx] =
            __float2half_rn(t[tx][ty + jj*8]);
}

// ---------------------------------------------------------------------------
// fp16 GEMM: CTA 128x128, 8 warps (2x4) of 64x32, K32 stages, 5-stage
// cp.async pipeline (CP_WAIT(3), uniform commit-groups), 1 sync/stage,
// ldmatrix A+B with hoisted fragments, fp32 accum.
// ---------------------------------------------------------------------------
#define NSTG 5
#define KS   32
#define TSH  40              // smem row stride, halves (80B: ldmatrix conflict-free)
#define T_HALVES (128*TSH)
#define STG_BYTES (2*T_HALVES*2)       // 20480
#define SMEM_GEMM (NSTG*STG_BYTES)     // 102400

template<int MODE>
__global__ __launch_bounds__(256, 2) void k_gemm(const __half* __restrict__ A,
                                                 const __half* __restrict__ Wt,
                                                 const float* __restrict__ bias,
                                                 float* __restrict__ C)
{
    extern __shared__ char smc[];
    const uint32_t sb = smem_u32(smc);
    const int tid = threadIdx.x;
    const int bm = blockIdx.y * 128;
    const int bn = blockIdx.x * 128;
    const int wid = tid >> 5, lane = tid & 31;
    const int wm = wid >> 2, wn = wid & 3;     // 2 x 4 warps, 64x32 tiles
    const int rq = lane >> 2, cq = lane & 3;
    const int j = lane >> 3, r = lane & 7;

    const uint32_t a_lm = ((wm*64 + (j&1)*8 + r)*TSH + (j>>1)*8) * 2;
    const uint32_t b_lm = ((wn*32 + (j>>1)*8 + r)*TSH + (j&1)*8) * 2;

    float acc[4][4][4] = {};

    auto issue = [&](int kt, int s) {
        if (kt < 32) {
            const int kof = kt * KS;
            uint32_t asp = sb + s*STG_BYTES;
            uint32_t bsp = asp + T_HALVES*2;
            #pragma unroll
            for (int i = 0; i < 2; i++) {
                int f = tid + i*256;
                int row = f >> 2, c = (f & 3) * 8;
                int gr = bm + row;
                CP16(asp + (row*TSH + c)*2, A + (size_t)gr*1024 + kof + c,
                     (gr < M1) ? 16 : 0);
            }
            #pragma unroll
            for (int i = 0; i < 2; i++) {
                int f = tid + i*256;
                int row = f >> 2, c = (f & 3) * 8;
                CP16(bsp + (row*TSH + c)*2,
                     Wt + (size_t)(bn + row)*1024 + kof + c, 16);
            }
        }
        CP_COMMIT();
    };

    issue(0, 0); issue(1, 1); issue(2, 2); issue(3, 3);

    int s = 0;
    for (int kt = 0; kt < 32; kt++) {
        CP_WAIT(3);                 // uniform groups: stage kt guaranteed done
        __syncthreads();
        {
            int s2 = s + 4; if (s2 >= NSTG) s2 -= NSTG;
            issue(kt + 4, s2);
        }
        const uint32_t asp = sb + s*STG_BYTES;
        const uint32_t bsp = asp + T_HALVES*2;

        // hoist LDSM for both k16 chunks, then run all mma
        unsigned af[2][4][4], bf[2][4][2];
        #pragma unroll
        for (int c = 0; c < 2; c++) {
            const int k0 = c * 16;
            #pragma unroll
            for (int mt = 0; mt < 4; mt++)
                LDSM4(af[c][mt][0], af[c][mt][1], af[c][mt][2], af[c][mt][3],
                      asp + a_lm + (mt*16*TSH + k0)*2);
            #pragma unroll
            for (int p = 0; p < 2; p++)
                LDSM4(bf[c][2*p][0], bf[c][2*p][1], bf[c][2*p+1][0], bf[c][2*p+1][1],
                      bsp + b_lm + (p*16*TSH + k0)*2);
        }
        #pragma unroll
        for (int c = 0; c < 2; c++)
            #pragma unroll
            for (int mt = 0; mt < 4; mt++)
                #pragma unroll
                for (int nt = 0; nt < 4; nt++)
                    mma_f16(acc[mt][nt], af[c][mt], bf[c][nt]);

        if (++s >= NSTG) s -= NSTG;
    }

    // ---- epilogue ----
    #pragma unroll
    for (int nt = 0; nt < 4; nt++) {
        const int gc = bn + wn*32 + nt*8 + 2*cq;
        const float b0 = bias[gc], b1 = bias[gc+1];
        int region = 0, h = 0, d0 = 0;
        if (MODE == 0) {
            region = gc >> 10;
            int w0 = gc & 1023;
            h = w0 >> 6; d0 = w0 & 63;
        }
        #pragma unroll
        for (int mt = 0; mt < 4; mt++) {
            #pragma unroll
            for (int half = 0; half < 2; half++) {
                int row = bm + wm*64 + mt*16 + rq + 8*half;
                if (row >= M1) continue;
                float x0 = acc[mt][nt][2*half]   + b0;
                float x1 = acc[mt][nt][2*half+1] + b1;
                if (MODE == 0) {
                    int b_ = row / SC;
                    int sdx = row - b_ * SC;
                    if (region == 0) {
                        size_t idx = (((size_t)b_*HEADSC + h)*SC + sdx)*HDIMC + d0;
                        *(unsigned*)(g_Qh + idx) = packh2(x0, x1);
                    } else if (region == 1) {
                        size_t idx = (((size_t)b_*HEADSC + h)*TC + (sdx+1))*HDIMC + d0;
                        *(unsigned*)(g_Kh + idx) = packh2(x0, x1);
                    } else {
                        size_t idx = (((size_t)b_*HEADSC + h)*HDIMC + d0)*TC + (sdx+1);
                        g_Vh[idx]        = __float2half_rn(x0);
                        g_Vh[idx + 1024] = __float2half_rn(x1);
                    }
                } else {
                    *(float2*)(C + (size_t)row*1024 + gc) = make_float2(x0, x1);
                }
            }
        }
    }
}

// ---------------------------------------------------------------------------
// image token K/V (fp32 compute, fp16 store; V transposed)
// ---------------------------------------------------------------------------
__global__ __launch_bounds__(256) void k_img(const float* __restrict__ img,
                                             const float* __restrict__ ukw,
                                             const float* __restrict__ ukb,
                                             const float* __restrict__ uvw,
                                             const float* __restrict__ uvb)
{
    int gw   = (blockIdx.x * blockDim.x + threadIdx.x) >> 5;
    int lane = threadIdx.x & 31;
    int which = gw >> 12;
    int rem = gw & 4095;
    int b_ = rem >> 10;
    int jj = rem & 1023;
    const float* w  = which ? uvw : ukw;
    const float* bb = which ? uvb : ukb;

    const float4* x4 = (const float4*)(img + (size_t)b_*1024);
    const float4* w4 = (const float4*)(w + (size_t)jj*1024);
    float s = 0.f;
    for (int e = lane; e < 256; e += 32) {
        float4 a = x4[e], b = w4[e];
        s += a.x*b.x + a.y*b.y + a.z*b.z + a.w*b.w;
    }
    #pragma unroll
    for (int o = 16; o; o >>= 1) s += __shfl_xor_sync(0xffffffffu, s, o);
    if (lane == 0) {
        int h = jj >> 6, d = jj & 63;
        __half v = __float2half_rn(s + bb[jj]);
        if (which)
            g_Vh[(((size_t)b_*HEADSC + h)*HDIMC + d)*TC + 0] = v;
        else
            g_Kh[(((size_t)b_*HEADSC + h)*TC + 0)*HDIMC + d] = v;
    }
}

// ---------------------------------------------------------------------------
// Attention fp16 (qt launched descending for tail pack)
// ---------------------------------------------------------------------------
#define AQ_B   0
#define AKV_B  9216
#define AMSK_B (AKV_B + 4*9216)
#define ARED_B (AMSK_B + 512)
#define SMEM_ATTN (ARED_B + 512)
#define QSTR 72

__global__ __launch_bounds__(128) void k_attn(const float* __restrict__ amask)
{
    extern __shared__ char smc[];
    const uint32_t sb = smem_u32(smc);
    float* mskp = (float*)(smc + AMSK_B);
    float* red  = (float*)(smc + ARED_B);
    float* obuf = (float*)(smc + AKV_B);

    const int tid = threadIdx.x;
    const int qt = 15 - blockIdx.x;          // longest CTAs first
    const int h = blockIdx.y, b_ = blockIdx.z;
    const int q0 = qt * 64;
    const __half* Qg = g_Qh + (((size_t)b_*HEADSC + h)*SC) * HDIMC;
    const __half* Kg = g_Kh + (((size_t)b_*HEADSC + h)*TC) * HDIMC;
    const __half* Vg = g_Vh + (((size_t)b_*HEADSC + h)*HDIMC) * TC;  // [d][t]

    const int wid = tid >> 5, lane = tid & 31;
    const int wm = wid >> 1, wn = wid & 1;
    const int rq = lane >> 2, cq = lane & 3;
    const int j = lane >> 3, r = lane & 7;

    #pragma unroll
    for (int i = 0; i < 4; i++) {
        int f = tid + i*128;
        int row = f >> 3, c = (f & 7) * 8;
        int gq = q0 + row;
        CP16(sb + AQ_B + (row*QSTR + c)*2, Qg + (size_t)gq*HDIMC + c,
             (gq < SC) ? 16 : 0);
    }
    CP_COMMIT();

    auto issueKV = [&](int kt, int bf) {
        int k0 = kt * 64;
        uint32_t kb = sb + AKV_B + bf*2*9216;
        uint32_t vb = kb + 9216;
        #pragma unroll
        for (int i = 0; i < 4; i++) {
            int f = tid + i*128;
            int row = f >> 3, c = (f & 7) * 8;
            CP16(kb + (row*QSTR + c)*2, Kg + (size_t)(k0+row)*HDIMC + c, 16);
            CP16(vb + (row*QSTR + c)*2, Vg + (size_t)row*TC + k0 + c, 16);
        }
        if (tid < 64) {
            int kk = k0 + tid;
            mskp[bf*64 + tid] = (kk == 0) ? 0.f : amask[(size_t)b_*SC + kk - 1];
        }
        CP_COMMIT();
    };

    issueKV(0, 0);

    unsigned qf[2][4][4];
    float o[2][8][4] = {};
    float lsum[2][2] = {};
    const int nkt = min(qt + 2, 16);

    for (int kt = 0; kt < nkt; kt++) {
        const int bf = kt & 1;
        __syncthreads();
        if (kt + 1 < nkt) { issueKV(kt + 1, bf ^ 1); CP_WAIT(1); }
        else              { CP_WAIT(0); }
        __syncthreads();

        if (kt == 0) {
            #pragma unroll
            for (int mt = 0; mt < 2; mt++)
                #pragma unroll
                for (int dc = 0; dc < 4; dc++)
                    LDSM4(qf[mt][dc][0], qf[mt][dc][1], qf[mt][dc][2], qf[mt][dc][3],
                          sb + AQ_B + ((wm*32 + mt*16 + (j&1)*8 + r)*QSTR
                                       + dc*16 + (j>>1)*8)*2);
        }

        const int k0 = kt * 64;
        if (k0 + wn*32 > q0 + wm*32 + 32) continue;

        const uint32_t kb = sb + AKV_B + bf*2*9216;
        const uint32_t vb = kb + 9216;

        float s_[2][4][4] = {};
        #pragma unroll
        for (int dc = 0; dc < 4; dc++) {
            unsigned kf[4][2];
            #pragma unroll
            for (int p = 0; p < 2; p++)
                LDSM4(kf[2*p][0], kf[2*p][1], kf[2*p+1][0], kf[2*p+1][1],
                      kb + ((wn*32 + p*16 + (j>>1)*8 + r)*QSTR
                            + dc*16 + (j&1)*8)*2);
            #pragma unroll
            for (int mt = 0; mt < 2; mt++)
                #pragma unroll
                for (int nt = 0; nt < 4; nt++)
                    mma_f16(s_[mt][nt], qf[mt][dc], kf[nt]);
        }

        unsigned pl[2][4][2];
        #pragma unroll
        for (int mt = 0; mt < 2; mt++) {
            const int gq0 = q0 + wm*32 + mt*16 + rq;
            #pragma unroll
            for (int nt = 0; nt < 4; nt++) {
                int lc = wn*32 + nt*8 + 2*cq;
                int gc = k0 + lc;
                float m0 = mskp[bf*64 + lc], m1 = mskp[bf*64 + lc + 1];
                float p00 = (gc     <= gq0+1) ? __expf(s_[mt][nt][0]*0.125f + m0) : 0.f;
                float p01 = (gc + 1 <= gq0+1) ? __expf(s_[mt][nt][1]*0.125f + m1) : 0.f;
                float p10 = (gc     <= gq0+9) ? __expf(s_[mt][nt][2]*0.125f + m0) : 0.f;
                float p11 = (gc + 1 <= gq0+9) ? __expf(s_[mt][nt][3]*0.125f + m1) : 0.f;
                lsum[mt][0] += p00 + p01;
                lsum[mt][1] += p10 + p11;
                pl[mt][nt][0] = packh2(p00, p01);
                pl[mt][nt][1] = packh2(p10, p11);
            }
        }

        #pragma unroll
        for (int kc = 0; kc < 2; kc++) {
            unsigned vf[8][2];
            #pragma unroll
            for (int p = 0; p < 4; p++)
                LDSM4(vf[2*p][0], vf[2*p][1], vf[2*p+1][0], vf[2*p+1][1],
                      vb + ((p*16 + (j>>1)*8 + r)*QSTR
                            + wn*32 + kc*16 + (j&1)*8)*2);
            #pragma unroll
            for (int mt = 0; mt < 2; mt++) {
                unsigned af[4];
                af[0] = pl[mt][2*kc][0];
                af[1] = pl[mt][2*kc][1];
                af[2] = pl[mt][2*kc+1][0];
                af[3] = pl[mt][2*kc+1][1];
                #pragma unroll
                for (int nt = 0; nt < 8; nt++)
                    mma_f16(o[mt][nt], af, vf[nt]);
            }
        }
    }

    #pragma unroll
    for (int mt = 0; mt < 2; mt++)
        #pragma unroll
        for (int i = 0; i < 2; i++) {
            lsum[mt][i] += __shfl_xor_sync(0xffffffffu, lsum[mt][i], 1);
            lsum[mt][i] += __shfl_xor_sync(0xffffffffu, lsum[mt][i], 2);
        }
    __syncthreads();
    if (cq == 0) {
        #pragma unroll
        for (int mt = 0; mt < 2; mt++) {
            int rr = wm*32 + mt*16 + rq;
            red[wn*64 + rr]     = lsum[mt][0];
            red[wn*64 + rr + 8] = lsum[mt][1];
        }
    }
    if (wn == 1) {
        #pragma unroll
        for (int mt = 0; mt < 2; mt++)
            #pragma unroll
            for (int nt = 0; nt < 8; nt++) {
                int rr = wm*32 + mt*16 + rq;
                int d = nt*8 + 2*cq;
                obuf[(rr    )*68 + d]     = o[mt][nt][0];
                obuf[(rr    )*68 + d + 1] = o[mt][nt][1];
                obuf[(rr + 8)*68 + d]     = o[mt][nt][2];
                obuf[(rr + 8)*68 + d + 1] = o[mt][nt][3];
            }
    }
    __syncthreads();

    if (wn == 0) {
        __half* AOg = g_AOh + (size_t)b_*SC*EMBEDC + h*HDIMC;
        #pragma unroll
        for (int mt = 0; mt < 2; mt++) {
            int rr = wm*32 + mt*16 + rq;
            float inv0 = 1.f / (red[rr]     + red[64 + rr]);
            float inv1 = 1.f / (red[rr + 8] + red[64 + rr + 8]);
            int s0 = q0 + rr;
            #pragma unroll
            for (int nt = 0; nt < 8; nt++) {
                int d = nt*8 + 2*cq;
                if (s0 < SC) {
                    float y0 = (o[mt][nt][0] + obuf[rr*68 + d])     * inv0;
                    float y1 = (o[mt][nt][1] + obuf[rr*68 + d + 1]) * inv0;
                    *(unsigned*)(AOg + (size_t)s0*EMBEDC + d) = packh2(y0, y1);
                }
                if (s0 + 8 < SC) {
                    float y2 = (o[mt][nt][2] + obuf[(rr+8)*68 + d])     * inv1;
                    float y3 = (o[mt][nt][3] + obuf[(rr+8)*68 + d + 1]) * inv1;
                    *(unsigned*)(AOg + (size_t)(s0+8)*EMBEDC + d) = packh2(y2, y3);
                }
            }
        }
    }
}

// ---------------------------------------------------------------------------
extern "C" void kernel_launch(void* const* d_in, const int* in_sizes, int n_in,
                              void* d_out, int out_size)
{
    (void)in_sizes; (void)n_in; (void)out_size;
    const float* word  = (const float*)d_in[0];
    const float* img   = (const float*)d_in[1];
    const float* amask = (const float*)d_in[2];
    const float* caw   = (const float*)d_in[3];
    const float* cab   = (const float*)d_in[4];
    const float* cpw   = (const float*)d_in[5];
    const float* cpb   = (const float*)d_in[6];
    const float* ukw   = (const float*)d_in[7];
    const float* ukb   = (const float*)d_in[8];
    const float* uvw   = (const float*)d_in[9];
    const float* uvb   = (const float*)d_in[10];
    float* out = (float*)d_out;

    void *p_Ah, *p_WTq, *p_WTp, *p_AO;
    cudaGetSymbolAddress(&p_Ah,  g_Ah);
    cudaGetSymbolAddress(&p_WTq, g_WTqh);
    cudaGetSymbolAddress(&p_WTp, g_WTph);
    cudaGetSymbolAddress(&p_AO,  g_AOh);

    cudaFuncSetAttribute(k_gemm<0>, cudaFuncAttributeMaxDynamicSharedMemorySize, SMEM_GEMM);
    cudaFuncSetAttribute(k_gemm<1>, cudaFuncAttributeMaxDynamicSharedMemorySize, SMEM_GEMM);
    cudaFuncSetAttribute(k_attn, cudaFuncAttributeMaxDynamicSharedMemorySize, SMEM_ATTN);

    k_cvtH<<<4092, 256>>>((const float4*)word, (uint2*)p_Ah);
    k_transpH<<<dim3(96, 32), 256>>>(caw, (__half*)p_WTq, 3072);
    k_transpH<<<dim3(32, 32), 256>>>(cpw, (__half*)p_WTp, 1024);

    k_gemm<0><<<dim3(24, 32), 256, SMEM_GEMM>>>(
        (const __half*)p_Ah, (const __half*)p_WTq, cab, nullptr);

    k_img<<<1024, 256>>>(img, ukw, ukb, uvw, uvb);

    dim3 ga(16, 16, 4);
    k_attn<<<ga, 128, SMEM_ATTN>>>(amask);

    k_gemm<1><<<dim3(8, 32), 256, SMEM_GEMM>>>(
        (const __half*)p_AO, (const __half*)p_WTp, cpb, out);
}

// round 17
// speedup vs baseline: 5.8494x; 1.0689x over previous
#include <cuda_runtime.h>
#include <cuda_fp16.h>
#include <cstdint>

#define EMBEDC 1024
#define HEADSC 16
#define HDIMC  64
#define BC     4
#define SC     1023
#define TC     1024
#define M1     (BC*SC)   // 4092

// Scratch (allocation-free rule: __device__ globals), all fp16
__device__ __align__(16) __half g_Qh[BC*HEADSC*SC*HDIMC];    // [b][h][s][d]
__device__ __align__(16) __half g_Kh[BC*HEADSC*TC*HDIMC];    // [b][h][t][d]
__device__ __align__(16) __half g_Vh[BC*HEADSC*HDIMC*TC];    // [b][h][d][t] transposed
__device__ __align__(16) __half g_AOh[BC*SC*EMBEDC];         // attn out (B,S,E)
__device__ __align__(16) __half g_Ah[M1*EMBEDC];             // word
__device__ __align__(16) __half g_WTqh[3*EMBEDC*EMBEDC];     // c_attn_w^T [n][k]
__device__ __align__(16) __half g_WTph[EMBEDC*EMBEDC];       // c_proj_w^T [n][k]

__device__ __forceinline__ unsigned packh2(float a, float b) {
    __half2 h = __floats2half2_rn(a, b);
    return *(unsigned*)&h;
}

__device__ __forceinline__ void mma_f16(float c[4], const unsigned a[4],
                                        const unsigned b[2]) {
    asm volatile(
        "mma.sync.aligned.m16n8k16.row.col.f32.f16.f16.f32 "
        "{%0,%1,%2,%3}, {%4,%5,%6,%7}, {%8,%9}, {%0,%1,%2,%3};"
        : "+f"(c[0]), "+f"(c[1]), "+f"(c[2]), "+f"(c[3])
        : "r"(a[0]), "r"(a[1]), "r"(a[2]), "r"(a[3]), "r"(b[0]), "r"(b[1]));
}

__device__ __forceinline__ uint32_t smem_u32(const void* p) {
    uint32_t a;
    asm("{ .reg .u64 t; cvta.to.shared.u64 t, %1; cvt.u32.u64 %0, t; }"
        : "=r"(a) : "l"(p));
    return a;
}
#define CP16(dst, src, sz) \
    asm volatile("cp.async.cg.shared.global [%0], [%1], 16, %2;" \
                 :: "r"(dst), "l"(src), "r"((uint32_t)(sz)) : "memory")
#define CP_COMMIT() asm volatile("cp.async.commit_group;" ::: "memory")
#define CP_WAIT(n)  asm volatile("cp.async.wait_group %0;" :: "n"(n) : "memory")
#define LDSM4(r0,r1,r2,r3, addr) \
    asm volatile("ldmatrix.sync.aligned.m8n8.x4.shared.b16 {%0,%1,%2,%3}, [%4];" \
                 : "=r"(r0),"=r"(r1),"=r"(r2),"=r"(r3) : "r"(addr))

// ---------------------------------------------------------------------------
// Prep: fp16 round-copy and transpose+round
// ---------------------------------------------------------------------------
__global__ __launch_bounds__(256) void k_cvtH(const float4* __restrict__ in,
                                              uint2* __restrict__ out)
{
    size_t i = (size_t)blockIdx.x * 256 + threadIdx.x;
    float4 v = in[i];
    out[i] = make_uint2(packh2(v.x, v.y), packh2(v.z, v.w));
}

__global__ __launch_bounds__(256) void k_transpH(const float* __restrict__ W,
                                                 __half* __restrict__ WT, int N)
{
    __shared__ float t[32][33];
    int bx = blockIdx.x * 32, by = blockIdx.y * 32;
    int tx = threadIdx.x & 31, ty = threadIdx.x >> 5;   // 32 x 8
    #pragma unroll
    for (int jj = 0; jj < 4; jj++)
        t[ty + jj*8][tx] = W[(size_t)(by + ty + jj*8) * N + bx + tx];
    __syncthreads();
    #pragma unroll
    for (int jj = 0; jj < 4; jj++)
        WT[(size_t)(bx + ty + jj*8) * 1024 + by + tx] =
            __float2half_rn(t[tx][ty + jj*8]);
}

// ---------------------------------------------------------------------------
// fp16 GEMM: CTA 128x128, 8 warps (2x4) of 64x32, K64 stages (16 of them),
// 3-stage cp.async pipeline (CP_WAIT(1), uniform groups), 1 sync/stage,
// ldmatrix A+B with pairwise-hoisted fragments, fp32 accum.
// ---------------------------------------------------------------------------
#define NSTG 3
#define KS   64
#define TSH  72              // smem row stride, halves (144B: ldmatrix conflict-free)
#define T_HALVES (128*TSH)   // 9216
#define STG_BYTES (2*T_HALVES*2)       // 36864
#define SMEM_GEMM (NSTG*STG_BYTES)     // 110592

template<int MODE>
__global__ __launch_bounds__(256, 2) void k_gemm(const __half* __restrict__ A,
                                                 const __half* __restrict__ Wt,
                                                 const float* __restrict__ bias,
                                                 float* __restrict__ C)
{
    extern __shared__ char smc[];
    const uint32_t sb = smem_u32(smc);
    const int tid = threadIdx.x;
    const int bm = blockIdx.y * 128;
    const int bn = blockIdx.x * 128;
    const int wid = tid >> 5, lane = tid & 31;
    const int wm = wid >> 2, wn = wid & 3;     // 2 x 4 warps, 64x32 tiles
    const int rq = lane >> 2, cq = lane & 3;
    const int j = lane >> 3, r = lane & 7;

    const uint32_t a_lm = ((wm*64 + (j&1)*8 + r)*TSH + (j>>1)*8) * 2;
    const uint32_t b_lm = ((wn*32 + (j>>1)*8 + r)*TSH + (j&1)*8) * 2;

    float acc[4][4][4] = {};

    auto issue = [&](int kt, int s) {
        if (kt < 16) {
            const int kof = kt * KS;
            uint32_t asp = sb + s*STG_BYTES;
            uint32_t bsp = asp + T_HALVES*2;
            #pragma unroll
            for (int i = 0; i < 4; i++) {
                int f = tid + i*256;
                int row = f >> 3, c = (f & 7) * 8;
                int gr = bm + row;
                CP16(asp + (row*TSH + c)*2, A + (size_t)gr*1024 + kof + c,
                     (gr < M1) ? 16 : 0);
            }
            #pragma unroll
            for (int i = 0; i < 4; i++) {
                int f = tid + i*256;
                int row = f >> 3, c = (f & 7) * 8;
                CP16(bsp + (row*TSH + c)*2,
                     Wt + (size_t)(bn + row)*1024 + kof + c, 16);
            }
        }
        CP_COMMIT();
    };

    issue(0, 0); issue(1, 1);

    int s = 0;
    for (int kt = 0; kt < 16; kt++) {
        CP_WAIT(1);                 // uniform groups: stage kt guaranteed done
        __syncthreads();
        {
            int s2 = s + 2; if (s2 >= NSTG) s2 -= NSTG;
            issue(kt + 2, s2);
        }
        const uint32_t asp = sb + s*STG_BYTES;
        const uint32_t bsp = asp + T_HALVES*2;

        // 4 k16 chunks, processed in hoisted pairs
        #pragma unroll
        for (int cp = 0; cp < 2; cp++) {
            unsigned af[2][4][4], bf[2][4][2];
            #pragma unroll
            for (int c = 0; c < 2; c++) {
                const int k0 = (cp*2 + c) * 16;
                #pragma unroll
                for (int mt = 0; mt < 4; mt++)
                    LDSM4(af[c][mt][0], af[c][mt][1], af[c][mt][2], af[c][mt][3],
                          asp + a_lm + (mt*16*TSH + k0)*2);
                #pragma unroll
                for (int p = 0; p < 2; p++)
                    LDSM4(bf[c][2*p][0], bf[c][2*p][1],
                          bf[c][2*p+1][0], bf[c][2*p+1][1],
                          bsp + b_lm + (p*16*TSH + k0)*2);
            }
            #pragma unroll
            for (int c = 0; c < 2; c++)
                #pragma unroll
                for (int mt = 0; mt < 4; mt++)
                    #pragma unroll
                    for (int nt = 0; nt < 4; nt++)
                        mma_f16(acc[mt][nt], af[c][mt], bf[c][nt]);
        }

        if (++s >= NSTG) s -= NSTG;
    }

    // ---- epilogue ----
    #pragma unroll
    for (int nt = 0; nt < 4; nt++) {
        const int gc = bn + wn*32 + nt*8 + 2*cq;
        const float b0 = bias[gc], b1 = bias[gc+1];
        int region = 0, h = 0, d0 = 0;
        if (MODE == 0) {
            region = gc >> 10;
            int w0 = gc & 1023;
            h = w0 >> 6; d0 = w0 & 63;
        }
        #pragma unroll
        for (int mt = 0; mt < 4; mt++) {
            #pragma unroll
            for (int half = 0; half < 2; half++) {
                int row = bm + wm*64 + mt*16 + rq + 8*half;
                if (row >= M1) continue;
                float x0 = acc[mt][nt][2*half]   + b0;
                float x1 = acc[mt][nt][2*half+1] + b1;
                if (MODE == 0) {
                    int b_ = row / SC;
                    int sdx = row - b_ * SC;
                    if (region == 0) {
                        size_t idx = (((size_t)b_*HEADSC + h)*SC + sdx)*HDIMC + d0;
                        *(unsigned*)(g_Qh + idx) = packh2(x0, x1);
                    } else if (region == 1) {
                        size_t idx = (((size_t)b_*HEADSC + h)*TC + (sdx+1))*HDIMC + d0;
                        *(unsigned*)(g_Kh + idx) = packh2(x0, x1);
                    } else {
                        size_t idx = (((size_t)b_*HEADSC + h)*HDIMC + d0)*TC + (sdx+1);
                        g_Vh[idx]        = __float2half_rn(x0);
                        g_Vh[idx + 1024] = __float2half_rn(x1);
                    }
                } else {
                    *(float2*)(C + (size_t)row*1024 + gc) = make_float2(x0, x1);
                }
            }
        }
    }
}

// ---------------------------------------------------------------------------
// image token K/V (fp32 compute, fp16 store; V transposed)
// ---------------------------------------------------------------------------
__global__ __launch_bounds__(256) void k_img(const float* __restrict__ img,
                                             const float* __restrict__ ukw,
                                             const float* __restrict__ ukb,
                                             const float* __restrict__ uvw,
                                             const float* __restrict__ uvb)
{
    int gw   = (blockIdx.x * blockDim.x + threadIdx.x) >> 5;
    int lane = threadIdx.x & 31;
    int which = gw >> 12;
    int rem = gw & 4095;
    int b_ = rem >> 10;
    int jj = rem & 1023;
    const float* w  = which ? uvw : ukw;
    const float* bb = which ? uvb : ukb;

    const float4* x4 = (const float4*)(img + (size_t)b_*1024);
    const float4* w4 = (const float4*)(w + (size_t)jj*1024);
    float s = 0.f;
    for (int e = lane; e < 256; e += 32) {
        float4 a = x4[e], b = w4[e];
        s += a.x*b.x + a.y*b.y + a.z*b.z + a.w*b.w;
    }
    #pragma unroll
    for (int o = 16; o; o >>= 1) s += __shfl_xor_sync(0xffffffffu, s, o);
    if (lane == 0) {
        int h = jj >> 6, d = jj & 63;
        __half v = __float2half_rn(s + bb[jj]);
        if (which)
            g_Vh[(((size_t)b_*HEADSC + h)*HDIMC + d)*TC + 0] = v;
        else
            g_Kh[(((size_t)b_*HEADSC + h)*TC + 0)*HDIMC + d] = v;
    }
}

// ---------------------------------------------------------------------------
// Attention fp16: 256 threads (8 warps, 4x2), 64-query tile, warp 16q x 32k.
// Q frags resident; P stays in registers; K/V double-buffered cp.async;
// O cross-warp reduced once at end. qt launched descending.
// Byte layout: Q 9216 | KV bufs 4*9216 | msk 512 | red 512
// ---------------------------------------------------------------------------
#define AQ_B   0
#define AKV_B  9216
#define AMSK_B (AKV_B + 4*9216)
#define ARED_B (AMSK_B + 512)
#define SMEM_ATTN (ARED_B + 512)
#define QSTR 72

__global__ __launch_bounds__(256) void k_attn(const float* __restrict__ amask)
{
    extern __shared__ char smc[];
    const uint32_t sb = smem_u32(smc);
    float* mskp = (float*)(smc + AMSK_B);
    float* red  = (float*)(smc + ARED_B);
    float* obuf = (float*)(smc + AKV_B);

    const int tid = threadIdx.x;
    const int qt = 15 - blockIdx.x;          // longest CTAs first
    const int h = blockIdx.y, b_ = blockIdx.z;
    const int q0 = qt * 64;
    const __half* Qg = g_Qh + (((size_t)b_*HEADSC + h)*SC) * HDIMC;
    const __half* Kg = g_Kh + (((size_t)b_*HEADSC + h)*TC) * HDIMC;
    const __half* Vg = g_Vh + (((size_t)b_*HEADSC + h)*HDIMC) * TC;  // [d][t]

    const int wid = tid >> 5, lane = tid & 31;
    const int wm = wid >> 1, wn = wid & 1;   // 4 x 2 warps: 16q x 32k
    const int rq = lane >> 2, cq = lane & 3;
    const int j = lane >> 3, r = lane & 7;

    // Q fill: 64 rows x 64 halves
    #pragma unroll
    for (int i = 0; i < 2; i++) {
        int f = tid + i*256;
        int row = f >> 3, c = (f & 7) * 8;
        int gq = q0 + row;
        CP16(sb + AQ_B + (row*QSTR + c)*2, Qg + (size_t)gq*HDIMC + c,
             (gq < SC) ? 16 : 0);
    }
    CP_COMMIT();

    auto issueKV = [&](int kt, int bf) {
        int k0 = kt * 64;
        uint32_t kb = sb + AKV_B + bf*2*9216;
        uint32_t vb = kb + 9216;
        #pragma unroll
        for (int i = 0; i < 2; i++) {
            int f = tid + i*256;
            int row = f >> 3, c = (f & 7) * 8;
            CP16(kb + (row*QSTR + c)*2, Kg + (size_t)(k0+row)*HDIMC + c, 16);
            CP16(vb + (row*QSTR + c)*2, Vg + (size_t)row*TC + k0 + c, 16);
        }
        if (tid < 64) {
            int kk = k0 + tid;
            mskp[bf*64 + tid] = (kk == 0) ? 0.f : amask[(size_t)b_*SC + kk - 1];
        }
        CP_COMMIT();
    };

    issueKV(0, 0);

    unsigned qf[4][4];           // Q fragments (4 d-chunks of k16)
    float o[8][4] = {};          // O accum: 16 rows x 64 d
    float lsum[2] = {};
    const int nkt = min(qt + 2, 16);

    for (int kt = 0; kt < nkt; kt++) {
        const int bf = kt & 1;
        __syncthreads();
        if (kt + 1 < nkt) { issueKV(kt + 1, bf ^ 1); CP_WAIT(1); }
        else              { CP_WAIT(0); }
        __syncthreads();

        if (kt == 0) {
            #pragma unroll
            for (int dc = 0; dc < 4; dc++)
                LDSM4(qf[dc][0], qf[dc][1], qf[dc][2], qf[dc][3],
                      sb + AQ_B + ((wm*16 + (j&1)*8 + r)*QSTR
                                   + dc*16 + (j>>1)*8)*2);
        }

        const int k0 = kt * 64;
        if (k0 + wn*32 > q0 + wm*16 + 16) continue;   // fully masked warp tile

        const uint32_t kb = sb + AKV_B + bf*2*9216;
        const uint32_t vb = kb + 9216;

        // S = Q K^T (16q x 32k)
        float s_[4][4] = {};
        #pragma unroll
        for (int dc = 0; dc < 4; dc++) {
            unsigned kf[4][2];
            #pragma unroll
            for (int p = 0; p < 2; p++)
                LDSM4(kf[2*p][0], kf[2*p][1], kf[2*p+1][0], kf[2*p+1][1],
                      kb + ((wn*32 + p*16 + (j>>1)*8 + r)*QSTR
                            + dc*16 + (j&1)*8)*2);
            #pragma unroll
            for (int nt = 0; nt < 4; nt++)
                mma_f16(s_[nt], qf[dc], kf[nt]);
        }

        // mask + exp -> P packed half2 (acc layout == A-frag layout)
        unsigned pl[4][2];
        {
            const int gq0 = q0 + wm*16 + rq;
            #pragma unroll
            for (int nt = 0; nt < 4; nt++) {
                int lc = wn*32 + nt*8 + 2*cq;
                int gc = k0 + lc;
                float m0 = mskp[bf*64 + lc], m1 = mskp[bf*64 + lc + 1];
                float p00 = (gc     <= gq0+1) ? __expf(s_[nt][0]*0.125f + m0) : 0.f;
                float p01 = (gc + 1 <= gq0+1) ? __expf(s_[nt][1]*0.125f + m1) : 0.f;
                float p10 = (gc     <= gq0+9) ? __expf(s_[nt][2]*0.125f + m0) : 0.f;
                float p11 = (gc + 1 <= gq0+9) ? __expf(s_[nt][3]*0.125f + m1) : 0.f;
                lsum[0] += p00 + p01;
                lsum[1] += p10 + p11;
                pl[nt][0] = packh2(p00, p01);
                pl[nt][1] = packh2(p10, p11);
            }
        }

        // O += P V (2 k16 chunks over this warp's 32 keys)
        #pragma unroll
        for (int kc = 0; kc < 2; kc++) {
            unsigned vf[8][2];
            #pragma unroll
            for (int p = 0; p < 4; p++)
                LDSM4(vf[2*p][0], vf[2*p][1], vf[2*p+1][0], vf[2*p+1][1],
                      vb + ((p*16 + (j>>1)*8 + r)*QSTR
                            + wn*32 + kc*16 + (j&1)*8)*2);
            unsigned af[4];
            af[0] = pl[2*kc][0];
            af[1] = pl[2*kc][1];
            af[2] = pl[2*kc+1][0];
            af[3] = pl[2*kc+1][1];
            #pragma unroll
            for (int nt = 0; nt < 8; nt++)
                mma_f16(o[nt], af, vf[nt]);
        }
    }

    // row sums: quad reduce, publish per wn
    #pragma unroll
    for (int i = 0; i < 2; i++) {
        lsum[i] += __shfl_xor_sync(0xffffffffu, lsum[i], 1);
        lsum[i] += __shfl_xor_sync(0xffffffffu, lsum[i], 2);
    }
    __syncthreads();                 // mainloop fully done; smem reusable
    if (cq == 0) {
        int rr = wm*16 + rq;
        red[wn*64 + rr]     = lsum[0];
        red[wn*64 + rr + 8] = lsum[1];
    }
    if (wn == 1) {
        #pragma unroll
        for (int nt = 0; nt < 8; nt++) {
            int rr = wm*16 + rq;
            int d = nt*8 + 2*cq;
            obuf[(rr    )*68 + d]     = o[nt][0];
            obuf[(rr    )*68 + d + 1] = o[nt][1];
            obuf[(rr + 8)*68 + d]     = o[nt][2];
            obuf[(rr + 8)*68 + d + 1] = o[nt][3];
        }
    }
    __syncthreads();

    if (wn == 0) {
        __half* AOg = g_AOh + (size_t)b_*SC*EMBEDC + h*HDIMC;
        int rr = wm*16 + rq;
        float inv0 = 1.f / (red[rr]     + red[64 + rr]);
        float inv1 = 1.f / (red[rr + 8] + red[64 + rr + 8]);
        int s0 = q0 + rr;
        #pragma unroll
        for (int nt = 0; nt < 8; nt++) {
            int d = nt*8 + 2*cq;
            if (s0 < SC) {
                float y0 = (o[nt][0] + obuf[rr*68 + d])     * inv0;
                float y1 = (o[nt][1] + obuf[rr*68 + d + 1]) * inv0;
                *(unsigned*)(AOg + (size_t)s0*EMBEDC + d) = packh2(y0, y1);
            }
            if (s0 + 8 < SC) {
                float y2 = (o[nt][2] + obuf[(rr+8)*68 + d])     * inv1;
                float y3 = (o[nt][3] + obuf[(rr+8)*68 + d + 1]) * inv1;
                *(unsigned*)(AOg + (size_t)(s0+8)*EMBEDC + d) = packh2(y2, y3);
            }
        }
    }
}

// ---------------------------------------------------------------------------
extern "C" void kernel_launch(void* const* d_in, const int* in_sizes, int n_in,
                              void* d_out, int out_size)
{
    (void)in_sizes; (void)n_in; (void)out_size;
    const float* word  = (const float*)d_in[0];
    const float* img   = (const float*)d_in[1];
    const float* amask = (const float*)d_in[2];
    const float* caw   = (const float*)d_in[3];
    const float* cab   = (const float*)d_in[4];
    const float* cpw   = (const float*)d_in[5];
    const float* cpb   = (const float*)d_in[6];
    const float* ukw   = (const float*)d_in[7];
    const float* ukb   = (const float*)d_in[8];
    const float* uvw   = (const float*)d_in[9];
    const float* uvb   = (const float*)d_in[10];
    float* out = (float*)d_out;

    void *p_Ah, *p_WTq, *p_WTp, *p_AO;
    cudaGetSymbolAddress(&p_Ah,  g_Ah);
    cudaGetSymbolAddress(&p_WTq, g_WTqh);
    cudaGetSymbolAddress(&p_WTp, g_WTph);
    cudaGetSymbolAddress(&p_AO,  g_AOh);

    cudaFuncSetAttribute(k_gemm<0>, cudaFuncAttributeMaxDynamicSharedMemorySize, SMEM_GEMM);
    cudaFuncSetAttribute(k_gemm<1>, cudaFuncAttributeMaxDynamicSharedMemorySize, SMEM_GEMM);
    cudaFuncSetAttribute(k_attn, cudaFuncAttributeMaxDynamicSharedMemorySize, SMEM_ATTN);

    k_cvtH<<<4092, 256>>>((const float4*)word, (uint2*)p_Ah);
    k_transpH<<<dim3(96, 32), 256>>>(caw, (__half*)p_WTq, 3072);
    k_transpH<<<dim3(32, 32), 256>>>(cpw, (__half*)p_WTp, 1024);

    k_gemm<0><<<dim3(24, 32), 256, SMEM_GEMM>>>(
        (const __half*)p_Ah, (const __half*)p_WTq, cab, nullptr);

    k_img<<<1024, 256>>>(img, ukw, ukb, uvw, uvb);

    dim3 ga(16, 16, 4);
    k_attn<<<ga, 256, SMEM_ATTN>>>(amask);

    k_gemm<1><<<dim3(8, 32), 256, SMEM_GEMM>>>(
        (const __half*)p_AO, (const __half*)p_WTp, cpb, out);
}